// round 4
// baseline (speedup 1.0000x reference)
#include <cuda_runtime.h>
#include <math.h>

#define B_    128
#define H_    64
#define W_    126
#define HW_   8064          // H_*W_
#define BC_   8192          // B_*64
#define NMODE 4096          // 64*64

typedef unsigned long long u64;

__device__ __forceinline__ float lo32(u64 v) { return __uint_as_float((unsigned)v); }
__device__ __forceinline__ float hi32(u64 v) { return __uint_as_float((unsigned)(v >> 32)); }
__device__ __forceinline__ void fma2(u64& d, u64 a, u64 b) {
    asm("fma.rn.f32x2 %0, %1, %2, %0;" : "+l"(d) : "l"(a), "l"(b));
}
__device__ __forceinline__ u64 pack2(float x) {
    u64 d; asm("mov.b64 %0, {%1, %1};" : "=l"(d) : "f"(x)); return d;
}

// ---------------- device scratch ----------------
__device__ __align__(16) float g_x  [BC_ * (size_t)HW_];   // spatial [bc][h][w]
__device__ __align__(16) float g_s1 [BC_ * (size_t)8192];  // staging A
__device__ __align__(16) float g_xf [BC_ * (size_t)8192];  // staging B
__device__ __align__(16) float g_xfm[NMODE * (size_t)16384]; // mode-major [mode][b*2+ri][i]
__device__ __align__(16) float g_wt [NMODE * (size_t)4096];  // [mode][i][o]
__device__ __align__(16) float g_fwdW[126 * 128];  // [w][n]  fwd width basis
__device__ __align__(16) float g_invW[128 * 128];  // [n][w]  inv width basis (padded)
__device__ __align__(16) float g_Gt  [128 * 128];  // [j][m]  fwd height basis^T
__device__ __align__(16) float g_G2t [128 * 128];  // [j][m]  inv height basis^T
__device__ __align__(16) float g_mw  [4096];       // effective sigmoid mask

// ---------------- basis precompute ----------------
__global__ void k_basis(const float* __restrict__ mwin) {
    int i = blockIdx.x * blockDim.x + threadIdx.x;
    const double PI2 = 6.283185307179586476925286766559;
    if (i < 126 * 128) {
        int w = i / 128, n = i % 128, k = n & 63;
        double th = PI2 * (double)(k * w) / 126.0;
        g_fwdW[i] = (n < 64) ? (float)cos(th) : (float)(-sin(th));
    }
    if (i < 128 * 128) {
        int j = i / 128, w = i % 128;
        float v = 0.f;
        if (w < 126) {
            int k = j & 63;
            double a = (k == 0 || k == 63) ? (1.0 / 126.0) : (2.0 / 126.0);
            double th = PI2 * (double)(k * w) / 126.0;
            v = (j < 64) ? (float)(a * cos(th)) : (float)(-a * sin(th));
        }
        g_invW[i] = v;
    }
    if (i < 128 * 128) {
        int j = i / 128, m = i % 128;
        int ky = m & 63, h = j & 63;
        double th = PI2 * (double)(ky * h) / 64.0;
        double c = cos(th), s = sin(th);
        g_Gt[i] = (float)((m < 64) ? ((j < 64) ? c : s) : ((j < 64) ? -s : c));
    }
    if (i < 128 * 128) {
        int j = i / 128, m = i % 128;
        int h = m & 63, ky = j & 63;
        double th = PI2 * (double)(ky * h) / 64.0;
        double c = cos(th) / 64.0, s = sin(th) / 64.0;
        g_G2t[i] = (float)((m < 64) ? ((j < 64) ? c : -s) : ((j < 64) ? s : c));
    }
    if (i < 4096) {
        int ky = i >> 6, kx = i & 63;
        float s1 = 1.f / (1.f + expf(-mwin[i]));
        if (kx == 0 || kx == 63) {
            float s2 = 1.f / (1.f + expf(-mwin[(((64 - ky) & 63) << 6) + kx]));
            s1 = 0.5f * (s1 + s2);
        }
        g_mw[i] = s1;
    }
}

// ---------------- encoder 1x1 conv 3 -> 64 ----------------
__global__ __launch_bounds__(256) void k_enc(const float* __restrict__ xin,
                                             const float* __restrict__ ew,
                                             const float* __restrict__ eb) {
    __shared__ float sx[3 * 126];
    __shared__ float sw[192];
    __shared__ float sb[64];
    int b = blockIdx.x >> 6, h = blockIdx.x & 63;
    int t = threadIdx.x;
    if (t < 192) sw[t] = ew[t];
    if (t < 64)  sb[t] = eb[t];
    for (int idx = t; idx < 378; idx += 256) {
        int j = idx / 126, w = idx % 126;
        sx[idx] = xin[(size_t)(b * 3 + j) * HW_ + h * 126 + w];
    }
    __syncthreads();
    for (int idx = t; idx < 64 * 126; idx += 256) {
        int c = idx / 126, w = idx % 126;
        float v = sb[c] + sw[c * 3] * sx[w] + sw[c * 3 + 1] * sx[126 + w]
                        + sw[c * 3 + 2] * sx[252 + w];
        g_x[(size_t)(b * 64 + c) * HW_ + h * 126 + w] = v;
    }
}

// ======================================================================
// forward width DFT (f32x2, N-paired): per CTA 1 bc
// C[h 64][n 128] = A[h][w] * fwdW[w][n],  K = 126
// As [64][130], Bs [126][128] (no dup). Thread: ty(32)x2 rows, tx(8)x8 u64
// ======================================================================
__global__ __launch_bounds__(256) void k_fwdW() {
    extern __shared__ float sm[];
    float* As = sm;              // [64][130]
    float* Bs = sm + 64 * 130;   // [126][128]
    int bc = blockIdx.x;
    int t = threadIdx.x;
    const float* src = g_x + (size_t)bc * HW_;
    for (int idx = t; idx < HW_; idx += 256) {
        int h = idx / 126, w = idx - h * 126;
        As[h * 130 + w] = src[idx];
    }
    for (int idx = t; idx < 126 * 128; idx += 256) Bs[idx] = g_fwdW[idx];
    __syncthreads();
    int ty = t >> 3, tx = t & 7;
    u64 acc[2][8];
#pragma unroll
    for (int r = 0; r < 2; r++)
#pragma unroll
        for (int c = 0; c < 8; c++) acc[r][c] = 0ull;
    const float* a0p = As + (ty * 2) * 130;
    const float* a1p = As + (ty * 2 + 1) * 130;
    const float* bp  = Bs + tx * 16;
#pragma unroll 2
    for (int k = 0; k < 126; k++) {
        u64 a0 = pack2(a0p[k]);
        u64 a1 = pack2(a1p[k]);
        const float* bk = bp + k * 128;
        ulonglong2 b0 = *(const ulonglong2*)(bk);
        ulonglong2 b1 = *(const ulonglong2*)(bk + 4);
        ulonglong2 b2 = *(const ulonglong2*)(bk + 8);
        ulonglong2 b3 = *(const ulonglong2*)(bk + 12);
        u64 bb[8] = {b0.x, b0.y, b1.x, b1.y, b2.x, b2.y, b3.x, b3.y};
#pragma unroll
        for (int c = 0; c < 8; c++) { fma2(acc[0][c], a0, bb[c]); fma2(acc[1][c], a1, bb[c]); }
    }
    int ri = tx >> 2, kx0 = (tx & 3) * 16;
    float* dst = g_s1 + (size_t)bc * 8192 + ri * 4096 + kx0;
#pragma unroll
    for (int r = 0; r < 2; r++) {
        int h = ty * 2 + r;
        float v[16];
#pragma unroll
        for (int c = 0; c < 8; c++) { v[2 * c] = lo32(acc[r][c]); v[2 * c + 1] = hi32(acc[r][c]); }
#pragma unroll
        for (int q = 0; q < 4; q++)
            *(float4*)(dst + h * 64 + q * 4) = make_float4(v[4 * q], v[4 * q + 1], v[4 * q + 2], v[4 * q + 3]);
    }
}

// ======================================================================
// height transform (f32x2, N-paired): per CTA 1 bc
// C[m 128][kx 64] = basis[m][j] * S[j][kx],  K = 128
// As = basis^T [j 128][m 128]+pad, Bs [j 128][kx 64]. ty(64)x2 rows, tx(4)x8 u64
// ======================================================================
__global__ __launch_bounds__(256) void k_hdft(int fwd) {
    extern __shared__ float sm[];
    float* As = sm;               // [128][130]
    float* Bs = sm + 128 * 130;   // [128][64]
    int bc = blockIdx.x;
    int t = threadIdx.x;
    const float* basisT = fwd ? g_Gt : g_G2t;
    const float* in  = fwd ? g_s1 : g_xf;
    float*       out = fwd ? g_xf : g_s1;
    for (int idx = t; idx < 16384; idx += 256) {
        int j = idx >> 7, m = idx & 127;
        As[j * 130 + m] = basisT[idx];
    }
    const float* src = in + (size_t)bc * 8192;
    for (int idx = t; idx < 8192; idx += 256) Bs[idx] = src[idx];
    __syncthreads();
    int ty = t >> 2, tx = t & 3;
    u64 acc[2][8];
#pragma unroll
    for (int r = 0; r < 2; r++)
#pragma unroll
        for (int c = 0; c < 8; c++) acc[r][c] = 0ull;
    const float* ap = As + ty * 2;
    const float* bp = Bs + tx * 16;
#pragma unroll 2
    for (int k = 0; k < 128; k++) {
        u64 a0 = pack2(ap[k * 130]);
        u64 a1 = pack2(ap[k * 130 + 1]);
        const float* bk = bp + k * 64;
        ulonglong2 b0 = *(const ulonglong2*)(bk);
        ulonglong2 b1 = *(const ulonglong2*)(bk + 4);
        ulonglong2 b2 = *(const ulonglong2*)(bk + 8);
        ulonglong2 b3 = *(const ulonglong2*)(bk + 12);
        u64 bb[8] = {b0.x, b0.y, b1.x, b1.y, b2.x, b2.y, b3.x, b3.y};
#pragma unroll
        for (int c = 0; c < 8; c++) { fma2(acc[0][c], a0, bb[c]); fma2(acc[1][c], a1, bb[c]); }
    }
    int kx0 = tx * 16;
    float* dst = out + (size_t)bc * 8192 + kx0;
#pragma unroll
    for (int r = 0; r < 2; r++) {
        int m = ty * 2 + r;
        float v[16];
#pragma unroll
        for (int c = 0; c < 8; c++) { v[2 * c] = lo32(acc[r][c]); v[2 * c + 1] = hi32(acc[r][c]); }
        if (fwd) {
            const float* wrow = g_mw + (m & 63) * 64 + kx0;
#pragma unroll
            for (int c = 0; c < 16; c++) v[c] *= wrow[c];
        }
#pragma unroll
        for (int q = 0; q < 4; q++)
            *(float4*)(dst + m * 64 + q * 4) = make_float4(v[4 * q], v[4 * q + 1], v[4 * q + 2], v[4 * q + 3]);
    }
}

// ---------------- transpose to mode-major ----------------
__global__ __launch_bounds__(256) void k_t1() {
    __shared__ float s[128 * 65];
    int b = blockIdx.x >> 6, ky = blockIdx.x & 63;
    int t = threadIdx.x;
    for (int idx = t; idx < 8192; idx += 256) {
        int i = idx >> 7, r = idx & 127, ri = r >> 6, kx = r & 63;
        s[(ri * 64 + i) * 65 + kx] =
            g_xf[(size_t)(b * 64 + i) * 8192 + ri * 4096 + ky * 64 + kx];
    }
    __syncthreads();
    for (int idx = t; idx < 8192; idx += 256) {
        int kx = idx >> 7, c = idx & 127;
        g_xfm[(size_t)(ky * 64 + kx) * 16384 + b * 128 + c] = s[c * 65 + kx];
    }
}

// ---------------- transpose back from mode-major ----------------
__global__ __launch_bounds__(256) void k_t2() {
    __shared__ float s[128 * 65];
    int b = blockIdx.x >> 6, ky = blockIdx.x & 63;
    int t = threadIdx.x;
    for (int idx = t; idx < 8192; idx += 256) {
        int kx = idx >> 7, c = idx & 127;
        s[c * 65 + kx] = g_s1[(size_t)(ky * 64 + kx) * 16384 + b * 128 + c];
    }
    __syncthreads();
    for (int idx = t; idx < 8192; idx += 256) {
        int o = idx >> 7, r = idx & 127, ri = r >> 6, kx = r & 63;
        g_xf[(size_t)(b * 64 + o) * 8192 + ri * 4096 + ky * 64 + kx] =
            s[(ri * 64 + o) * 65 + kx];
    }
}

// ---------------- weight fold: wt[mode][i][o] = spec[i][o][mode] + mlp[o][i] ----------------
__global__ void k_wt(const float* __restrict__ spec, const float* __restrict__ mlp) {
    __shared__ float tile[32][33];
    int x = blockIdx.x * 32 + threadIdx.x;   // mode
    int yb = blockIdx.y * 32;                // io
#pragma unroll
    for (int j = 0; j < 32; j += 8)
        tile[threadIdx.y + j][threadIdx.x] = spec[(size_t)(yb + threadIdx.y + j) * 4096 + x];
    __syncthreads();
    int io2 = yb + threadIdx.x;
    float madd = mlp[(io2 & 63) * 64 + (io2 >> 6)];
    int mb = blockIdx.x * 32;
#pragma unroll
    for (int j = 0; j < 32; j += 8)
        g_wt[(size_t)(mb + threadIdx.y + j) * 4096 + io2] =
            tile[threadIdx.x][threadIdx.y + j] + madd;
}

// ======================================================================
// per-mode GEMM (f32x2, N-paired): C[256 x 64] = X[256 x 64] W[64 x 64]
// As [row 256][k 64]+pad, Bs [k 64][o 64]. ty(64)x4 rows, tx(4)x8 u64
// ======================================================================
__global__ __launch_bounds__(256) void k_sgemm() {
    extern __shared__ float sm[];
    float* As = sm;             // [256][65]
    float* Bs = sm + 256 * 65;  // [64][64]
    int mode = blockIdx.x, t = threadIdx.x;
    const float* asrc = g_xfm + (size_t)mode * 16384;
    const float* wsrc = g_wt + (size_t)mode * 4096;
    for (int idx = t; idx < 16384; idx += 256) {
        int row = idx >> 6, i = idx & 63;
        As[row * 65 + i] = asrc[idx];
    }
    for (int idx = t; idx < 4096; idx += 256) Bs[idx] = wsrc[idx];
    __syncthreads();
    int ty = t >> 2, tx = t & 3;
    u64 acc[4][8];
#pragma unroll
    for (int r = 0; r < 4; r++)
#pragma unroll
        for (int c = 0; c < 8; c++) acc[r][c] = 0ull;
    const float* ap = As + (ty * 4) * 65;
    const float* bp = Bs + tx * 16;
#pragma unroll 2
    for (int k = 0; k < 64; k++) {
        u64 aa[4];
#pragma unroll
        for (int r = 0; r < 4; r++) aa[r] = pack2(ap[r * 65 + k]);
        const float* bk = bp + k * 64;
        ulonglong2 b0 = *(const ulonglong2*)(bk);
        ulonglong2 b1 = *(const ulonglong2*)(bk + 4);
        ulonglong2 b2 = *(const ulonglong2*)(bk + 8);
        ulonglong2 b3 = *(const ulonglong2*)(bk + 12);
        u64 bb[8] = {b0.x, b0.y, b1.x, b1.y, b2.x, b2.y, b3.x, b3.y};
#pragma unroll
        for (int r = 0; r < 4; r++)
#pragma unroll
            for (int c = 0; c < 8; c++) fma2(acc[r][c], aa[r], bb[c]);
    }
    float* dst = g_s1 + (size_t)mode * 16384 + tx * 16;
#pragma unroll
    for (int r = 0; r < 4; r++) {
        int row = ty * 4 + r;
        float v[16];
#pragma unroll
        for (int c = 0; c < 8; c++) { v[2 * c] = lo32(acc[r][c]); v[2 * c + 1] = hi32(acc[r][c]); }
#pragma unroll
        for (int q = 0; q < 4; q++)
            *(float4*)(dst + row * 64 + q * 4) = make_float4(v[4 * q], v[4 * q + 1], v[4 * q + 2], v[4 * q + 3]);
    }
}

// ======================================================================
// inverse width + bias + exact GELU (f32x2, N-paired): per CTA 1 bc
// C[h 64][w 126] = U[h][n] * invW[n][w],  K = 128
// As [h 64][n 128]+pad, Bs = invW [128][128]. ty(32)x2 rows, tx(8)x8 u64
// ======================================================================
__global__ __launch_bounds__(256) void k_inv(const float* __restrict__ sb,
                                             const float* __restrict__ mb) {
    extern __shared__ float sm[];
    float* As = sm;              // [64][130]
    float* Bs = sm + 64 * 130;   // [128][128]
    int bc = blockIdx.x;
    int t = threadIdx.x;
    const float* src = g_s1 + (size_t)bc * 8192;
    for (int idx = t; idx < 8192; idx += 256) {
        int ri = idx >> 12, h = (idx >> 6) & 63, kx = idx & 63;
        As[h * 130 + ri * 64 + kx] = src[idx];
    }
    for (int idx = t; idx < 16384; idx += 256) Bs[idx] = g_invW[idx];
    __syncthreads();
    int ty = t >> 3, tx = t & 7;
    u64 acc[2][8];
#pragma unroll
    for (int r = 0; r < 2; r++)
#pragma unroll
        for (int c = 0; c < 8; c++) acc[r][c] = 0ull;
    const float* a0p = As + (ty * 2) * 130;
    const float* a1p = As + (ty * 2 + 1) * 130;
    const float* bp  = Bs + tx * 16;
#pragma unroll 2
    for (int k = 0; k < 128; k++) {
        u64 a0 = pack2(a0p[k]);
        u64 a1 = pack2(a1p[k]);
        const float* bk = bp + k * 128;
        ulonglong2 b0 = *(const ulonglong2*)(bk);
        ulonglong2 b1 = *(const ulonglong2*)(bk + 4);
        ulonglong2 b2 = *(const ulonglong2*)(bk + 8);
        ulonglong2 b3 = *(const ulonglong2*)(bk + 12);
        u64 bb[8] = {b0.x, b0.y, b1.x, b1.y, b2.x, b2.y, b3.x, b3.y};
#pragma unroll
        for (int c = 0; c < 8; c++) { fma2(acc[0][c], a0, bb[c]); fma2(acc[1][c], a1, bb[c]); }
    }
    int ch = bc & 63;
    float bias = __ldg(sb + ch) + __ldg(mb + ch);
    int w0 = tx * 16;
    float* dst = g_x + (size_t)bc * HW_;
#pragma unroll
    for (int r = 0; r < 2; r++) {
        int h = ty * 2 + r;
        float* row = dst + h * 126;
#pragma unroll
        for (int c = 0; c < 8; c++) {
            int w = w0 + 2 * c;
            if (w < 126) {
                float v0 = lo32(acc[r][c]) + bias;
                float v1 = hi32(acc[r][c]) + bias;
                float g0 = 0.5f * v0 * (1.0f + erff(v0 * 0.70710678118654752f));
                float g1 = 0.5f * v1 * (1.0f + erff(v1 * 0.70710678118654752f));
                *(float2*)(row + w) = make_float2(g0, g1);
            }
        }
    }
}

// ---------------- decoder 1x1 conv 64 -> 1 ----------------
__global__ __launch_bounds__(256) void k_dec(const float* __restrict__ dw,
                                             const float* __restrict__ db,
                                             float* __restrict__ out) {
    __shared__ float sw[64];
    int b = blockIdx.x, t = threadIdx.x;
    if (t < 64) sw[t] = dw[t];
    __syncthreads();
    float bias = __ldg(db);
    for (int p = t; p < HW_; p += 256) {
        float s = bias;
        const float* base = g_x + (size_t)b * 64 * HW_ + p;
#pragma unroll 8
        for (int c = 0; c < 64; c++) s = fmaf(sw[c], base[(size_t)c * HW_], s);
        out[(size_t)b * HW_ + p] = s;
    }
}

extern "C" void kernel_launch(void* const* d_in, const int* in_sizes, int n_in,
                              void* d_out, int out_size) {
    const float* x       = (const float*)d_in[0];
    const float* mode_w  = (const float*)d_in[1];
    const float* enc_w   = (const float*)d_in[2];
    const float* enc_b   = (const float*)d_in[3];
    const float* dec_w   = (const float*)d_in[4];
    const float* dec_b   = (const float*)d_in[5];
    const float* spec_w  = (const float*)d_in[6];
    const float* spec_b  = (const float*)d_in[7];
    const float* mlp_w   = (const float*)d_in[8];
    const float* mlp_b   = (const float*)d_in[9];
    float* out = (float*)d_out;

    const int smemF = (64 * 130 + 126 * 128) * 4;   // ~95.5KB  -> 2 CTA/SM
    const int smemH = (128 * 130 + 8192) * 4;       // ~97.0KB  -> 2 CTA/SM
    const int smemG = (256 * 65 + 4096) * 4;        // ~81.0KB  -> 2 CTA/SM
    const int smemI = (64 * 130 + 16384) * 4;       // ~96.5KB  -> 2 CTA/SM
    cudaFuncSetAttribute(k_fwdW,  cudaFuncAttributeMaxDynamicSharedMemorySize, smemF);
    cudaFuncSetAttribute(k_hdft,  cudaFuncAttributeMaxDynamicSharedMemorySize, smemH);
    cudaFuncSetAttribute(k_sgemm, cudaFuncAttributeMaxDynamicSharedMemorySize, smemG);
    cudaFuncSetAttribute(k_inv,   cudaFuncAttributeMaxDynamicSharedMemorySize, smemI);

    k_basis<<<64, 256>>>(mode_w);
    k_enc<<<8192, 256>>>(x, enc_w, enc_b);

    for (int l = 0; l < 4; l++) {
        k_wt<<<dim3(128, 128), dim3(32, 8)>>>(spec_w + (size_t)l * 16777216,
                                              mlp_w + (size_t)l * 4096);
        k_fwdW<<<8192, 256, smemF>>>();
        k_hdft<<<8192, 256, smemH>>>(1);
        k_t1<<<8192, 256>>>();
        k_sgemm<<<4096, 256, smemG>>>();
        k_t2<<<8192, 256>>>();
        k_hdft<<<8192, 256, smemH>>>(0);
        k_inv<<<8192, 256, smemI>>>(spec_b + l * 64, mlp_b + l * 64);
    }
    k_dec<<<128, 256>>>(dec_w, dec_b, out);
}

// round 6
// speedup vs baseline: 2.0803x; 2.0803x over previous
#include <cuda_runtime.h>
#include <math.h>

#define HW_   8064          // 64*126
#define BC_   8192          // 128*64
#define NMODE 4096          // 64*64

typedef unsigned long long u64;

__device__ __forceinline__ float lo32(u64 v) { return __uint_as_float((unsigned)v); }
__device__ __forceinline__ float hi32(u64 v) { return __uint_as_float((unsigned)(v >> 32)); }
__device__ __forceinline__ void fma2(u64& d, u64 a, u64 b) {
    asm("fma.rn.f32x2 %0, %1, %2, %0;" : "+l"(d) : "l"(a), "l"(b));
}
__device__ __forceinline__ u64 pack2(float x) {
    u64 d; asm("mov.b64 %0, {%1, %1};" : "=l"(d) : "f"(x)); return d;
}

// ---------------- device scratch ----------------
__device__ __align__(16) float g_x  [BC_ * (size_t)HW_];
__device__ __align__(16) float g_s1 [BC_ * (size_t)8192];
__device__ __align__(16) float g_xf [BC_ * (size_t)8192];
__device__ __align__(16) float g_xfm[NMODE * (size_t)16384];
__device__ __align__(16) float g_wt [NMODE * (size_t)4096];
__device__ __align__(16) float g_fwdW[126 * 128];  // [w][n]
__device__ __align__(16) float g_invW[128 * 128];  // [n][w]
__device__ __align__(16) float g_Gt  [128 * 128];  // [j][m]
__device__ __align__(16) float g_G2t [128 * 128];  // [j][m]
__device__ __align__(16) float g_mw  [4096];

// ---------------- basis precompute ----------------
__global__ void k_basis(const float* __restrict__ mwin) {
    int i = blockIdx.x * blockDim.x + threadIdx.x;
    const double PI2 = 6.283185307179586476925286766559;
    if (i < 126 * 128) {
        int w = i / 128, n = i % 128, k = n & 63;
        double th = PI2 * (double)(k * w) / 126.0;
        g_fwdW[i] = (n < 64) ? (float)cos(th) : (float)(-sin(th));
    }
    if (i < 128 * 128) {
        int j = i / 128, w = i % 128;
        float v = 0.f;
        if (w < 126) {
            int k = j & 63;
            double a = (k == 0 || k == 63) ? (1.0 / 126.0) : (2.0 / 126.0);
            double th = PI2 * (double)(k * w) / 126.0;
            v = (j < 64) ? (float)(a * cos(th)) : (float)(-a * sin(th));
        }
        g_invW[i] = v;
    }
    if (i < 128 * 128) {
        int j = i / 128, m = i % 128;
        int ky = m & 63, h = j & 63;
        double th = PI2 * (double)(ky * h) / 64.0;
        double c = cos(th), s = sin(th);
        g_Gt[i] = (float)((m < 64) ? ((j < 64) ? c : s) : ((j < 64) ? -s : c));
    }
    if (i < 128 * 128) {
        int j = i / 128, m = i % 128;
        int h = m & 63, ky = j & 63;
        double th = PI2 * (double)(ky * h) / 64.0;
        double c = cos(th) / 64.0, s = sin(th) / 64.0;
        g_G2t[i] = (float)((m < 64) ? ((j < 64) ? c : -s) : ((j < 64) ? s : c));
    }
    if (i < 4096) {
        int ky = i >> 6, kx = i & 63;
        float s1 = 1.f / (1.f + expf(-mwin[i]));
        if (kx == 0 || kx == 63) {
            float s2 = 1.f / (1.f + expf(-mwin[(((64 - ky) & 63) << 6) + kx]));
            s1 = 0.5f * (s1 + s2);
        }
        g_mw[i] = s1;
    }
}

// ---------------- encoder 1x1 conv 3 -> 64 ----------------
__global__ __launch_bounds__(256) void k_enc(const float* __restrict__ xin,
                                             const float* __restrict__ ew,
                                             const float* __restrict__ eb) {
    __shared__ float sx[3 * 126];
    __shared__ float sw[192];
    __shared__ float sb[64];
    int b = blockIdx.x >> 6, h = blockIdx.x & 63;
    int t = threadIdx.x;
    if (t < 192) sw[t] = ew[t];
    if (t < 64)  sb[t] = eb[t];
    for (int idx = t; idx < 378; idx += 256) {
        int j = idx / 126, w = idx % 126;
        sx[idx] = xin[(size_t)(b * 3 + j) * HW_ + h * 126 + w];
    }
    __syncthreads();
    for (int idx = t; idx < 64 * 126; idx += 256) {
        int c = idx / 126, w = idx % 126;
        float v = sb[c] + sw[c * 3] * sx[w] + sw[c * 3 + 1] * sx[126 + w]
                        + sw[c * 3 + 2] * sx[252 + w];
        g_x[(size_t)(b * 64 + c) * HW_ + h * 126 + w] = v;
    }
}

// ======================================================================
// GEMM inner-loop macro: 8x8 tile, M-paired FFMA2
// ======================================================================
#define GEMM_STEP(ap, bp, SA, SB, kk)                                        \
    {                                                                        \
        ulonglong2 av0 = *(const ulonglong2*)((ap) + (kk) * (SA));           \
        ulonglong2 av1 = *(const ulonglong2*)((ap) + (kk) * (SA) + 4);       \
        u64 aa0 = av0.x, aa1 = av0.y, aa2 = av1.x, aa3 = av1.y;              \
        float4 b0 = *(const float4*)((bp) + (kk) * (SB));                    \
        float4 b1 = *(const float4*)((bp) + (kk) * (SB) + 4);                \
        u64 bb[8] = {pack2(b0.x), pack2(b0.y), pack2(b0.z), pack2(b0.w),     \
                     pack2(b1.x), pack2(b1.y), pack2(b1.z), pack2(b1.w)};    \
        _Pragma("unroll")                                                    \
        for (int c = 0; c < 8; c++) {                                        \
            fma2(acc[0][c], aa0, bb[c]);                                     \
            fma2(acc[1][c], aa1, bb[c]);                                     \
            fma2(acc[2][c], aa2, bb[c]);                                     \
            fma2(acc[3][c], aa3, bb[c]);                                     \
        }                                                                    \
    }

// ======================================================================
// forward width DFT: C[h 64][n 128] = x[h][w] * fwdW[w][n], K=126
// As = x^T [126 w][68], Bs = fwdW [126][128]. 128 thr: mb=t>>4, nb=t&15
// ======================================================================
__global__ __launch_bounds__(128) void k_fwdW() {
    extern __shared__ float sm[];
    float* As = sm;              // [126][68]
    float* Bs = sm + 126 * 68;   // [126][128]
    int bc = blockIdx.x, t = threadIdx.x;
    const float* src = g_x + (size_t)bc * HW_;
    for (int idx = t; idx < HW_; idx += 128) {
        int h = idx / 126, w = idx - h * 126;
        As[w * 68 + h] = src[idx];
    }
    for (int idx = t; idx < 126 * 128; idx += 128) Bs[idx] = g_fwdW[idx];
    __syncthreads();
    int mb = t >> 4, nb = t & 15;
    u64 acc[4][8];
#pragma unroll
    for (int r = 0; r < 4; r++)
#pragma unroll
        for (int c = 0; c < 8; c++) acc[r][c] = 0ull;
    const float* ap = As + mb * 8;
    const float* bp = Bs + nb * 8;
#pragma unroll 2
    for (int k = 0; k < 126; k++) GEMM_STEP(ap, bp, 68, 128, k)
    int ri = nb >> 3, kx0 = (nb & 7) * 8;
    float* dst = g_s1 + (size_t)bc * 8192 + ri * 4096 + kx0;
#pragma unroll
    for (int r = 0; r < 4; r++) {
        int h0 = mb * 8 + 2 * r;
        float lo[8], hi[8];
#pragma unroll
        for (int c = 0; c < 8; c++) { lo[c] = lo32(acc[r][c]); hi[c] = hi32(acc[r][c]); }
        *(float4*)(dst + h0 * 64)           = make_float4(lo[0], lo[1], lo[2], lo[3]);
        *(float4*)(dst + h0 * 64 + 4)       = make_float4(lo[4], lo[5], lo[6], lo[7]);
        *(float4*)(dst + (h0 + 1) * 64)     = make_float4(hi[0], hi[1], hi[2], hi[3]);
        *(float4*)(dst + (h0 + 1) * 64 + 4) = make_float4(hi[4], hi[5], hi[6], hi[7]);
    }
}

// ======================================================================
// height transform: C[m 128][kx 64] = basis[m][j] * S[j][kx], K=128
// As = basis^T [128 j][132], Bs = S [128][64]. 128 thr: mb=t>>3, nb=t&7
// ======================================================================
__global__ __launch_bounds__(128) void k_hdft(int fwd) {
    extern __shared__ float sm[];
    float* As = sm;               // [128][132]
    float* Bs = sm + 128 * 132;   // [128][64]
    int bc = blockIdx.x, t = threadIdx.x;
    const float* basisT = fwd ? g_Gt : g_G2t;
    const float* in  = fwd ? g_s1 : g_xf;
    float*       out = fwd ? g_xf : g_s1;
    for (int idx = t; idx < 16384; idx += 128) {
        int j = idx >> 7, m = idx & 127;
        As[j * 132 + m] = basisT[idx];
    }
    const float* src = in + (size_t)bc * 8192;
    for (int idx = t; idx < 8192; idx += 128) Bs[idx] = src[idx];
    __syncthreads();
    int mb = t >> 3, nb = t & 7;
    u64 acc[4][8];
#pragma unroll
    for (int r = 0; r < 4; r++)
#pragma unroll
        for (int c = 0; c < 8; c++) acc[r][c] = 0ull;
    const float* ap = As + mb * 8;
    const float* bp = Bs + nb * 8;
#pragma unroll 2
    for (int k = 0; k < 128; k++) GEMM_STEP(ap, bp, 132, 64, k)
    int kx0 = nb * 8;
    float* dst = out + (size_t)bc * 8192 + kx0;
#pragma unroll
    for (int r = 0; r < 4; r++) {
        int m0 = mb * 8 + 2 * r;
        float lo[8], hi[8];
#pragma unroll
        for (int c = 0; c < 8; c++) { lo[c] = lo32(acc[r][c]); hi[c] = hi32(acc[r][c]); }
        if (fwd) {
            const float* w0 = g_mw + (m0 & 63) * 64 + kx0;
            const float* w1 = g_mw + ((m0 + 1) & 63) * 64 + kx0;
#pragma unroll
            for (int c = 0; c < 8; c++) { lo[c] *= w0[c]; hi[c] *= w1[c]; }
        }
        *(float4*)(dst + m0 * 64)           = make_float4(lo[0], lo[1], lo[2], lo[3]);
        *(float4*)(dst + m0 * 64 + 4)       = make_float4(lo[4], lo[5], lo[6], lo[7]);
        *(float4*)(dst + (m0 + 1) * 64)     = make_float4(hi[0], hi[1], hi[2], hi[3]);
        *(float4*)(dst + (m0 + 1) * 64 + 4) = make_float4(hi[4], hi[5], hi[6], hi[7]);
    }
}

// ---------------- transpose to mode-major ----------------
__global__ __launch_bounds__(256) void k_t1() {
    __shared__ float s[128 * 65];
    int b = blockIdx.x >> 6, ky = blockIdx.x & 63;
    int t = threadIdx.x;
    for (int idx = t; idx < 8192; idx += 256) {
        int i = idx >> 7, r = idx & 127, ri = r >> 6, kx = r & 63;
        s[(ri * 64 + i) * 65 + kx] =
            g_xf[(size_t)(b * 64 + i) * 8192 + ri * 4096 + ky * 64 + kx];
    }
    __syncthreads();
    for (int idx = t; idx < 8192; idx += 256) {
        int kx = idx >> 7, c = idx & 127;
        g_xfm[(size_t)(ky * 64 + kx) * 16384 + b * 128 + c] = s[c * 65 + kx];
    }
}

// ---------------- transpose back from mode-major ----------------
__global__ __launch_bounds__(256) void k_t2() {
    __shared__ float s[128 * 65];
    int b = blockIdx.x >> 6, ky = blockIdx.x & 63;
    int t = threadIdx.x;
    for (int idx = t; idx < 8192; idx += 256) {
        int kx = idx >> 7, c = idx & 127;
        s[c * 65 + kx] = g_s1[(size_t)(ky * 64 + kx) * 16384 + b * 128 + c];
    }
    __syncthreads();
    for (int idx = t; idx < 8192; idx += 256) {
        int o = idx >> 7, r = idx & 127, ri = r >> 6, kx = r & 63;
        g_xf[(size_t)(b * 64 + o) * 8192 + ri * 4096 + ky * 64 + kx] =
            s[(ri * 64 + o) * 65 + kx];
    }
}

// ---------------- weight fold ----------------
__global__ void k_wt(const float* __restrict__ spec, const float* __restrict__ mlp) {
    __shared__ float tile[32][33];
    int x = blockIdx.x * 32 + threadIdx.x;   // mode
    int yb = blockIdx.y * 32;                // io
#pragma unroll
    for (int j = 0; j < 32; j += 8)
        tile[threadIdx.y + j][threadIdx.x] = spec[(size_t)(yb + threadIdx.y + j) * 4096 + x];
    __syncthreads();
    int io2 = yb + threadIdx.x;
    float madd = mlp[(io2 & 63) * 64 + (io2 >> 6)];
    int mb = blockIdx.x * 32;
#pragma unroll
    for (int j = 0; j < 32; j += 8)
        g_wt[(size_t)(mb + threadIdx.y + j) * 4096 + io2] =
            tile[threadIdx.x][threadIdx.y + j] + madd;
}

// ======================================================================
// per-mode GEMM: C[256 x 64] = X[256 x 64] W[64 x 64], K=64
// As = X^T [64 i][260], Bs = W [64][64]. 256 thr: mb=t>>3 (32), nb=t&7
// ======================================================================
__global__ __launch_bounds__(256) void k_sgemm() {
    extern __shared__ float sm[];
    float* As = sm;             // [64][260]
    float* Bs = sm + 64 * 260;  // [64][64]
    int mode = blockIdx.x, t = threadIdx.x;
    const float* asrc = g_xfm + (size_t)mode * 16384;
    const float* wsrc = g_wt + (size_t)mode * 4096;
    for (int idx = t; idx < 16384; idx += 256) {
        int row = idx >> 6, i = idx & 63;
        As[i * 260 + row] = asrc[idx];
    }
    for (int idx = t; idx < 4096; idx += 256) Bs[idx] = wsrc[idx];
    __syncthreads();
    int mb = t >> 3, nb = t & 7;
    u64 acc[4][8];
#pragma unroll
    for (int r = 0; r < 4; r++)
#pragma unroll
        for (int c = 0; c < 8; c++) acc[r][c] = 0ull;
    const float* ap = As + mb * 8;
    const float* bp = Bs + nb * 8;
#pragma unroll 2
    for (int k = 0; k < 64; k++) GEMM_STEP(ap, bp, 260, 64, k)
    int o0 = nb * 8;
    float* dst = g_s1 + (size_t)mode * 16384 + o0;
#pragma unroll
    for (int r = 0; r < 4; r++) {
        int row0 = mb * 8 + 2 * r;
        float lo[8], hi[8];
#pragma unroll
        for (int c = 0; c < 8; c++) { lo[c] = lo32(acc[r][c]); hi[c] = hi32(acc[r][c]); }
        *(float4*)(dst + row0 * 64)           = make_float4(lo[0], lo[1], lo[2], lo[3]);
        *(float4*)(dst + row0 * 64 + 4)       = make_float4(lo[4], lo[5], lo[6], lo[7]);
        *(float4*)(dst + (row0 + 1) * 64)     = make_float4(hi[0], hi[1], hi[2], hi[3]);
        *(float4*)(dst + (row0 + 1) * 64 + 4) = make_float4(hi[4], hi[5], hi[6], hi[7]);
    }
}

// ======================================================================
// inverse width + bias + exact GELU: C[h 64][w 126] = U[h][n] * invW[n][w]
// As = U^T [128 n][68], Bs = invW [128][128]. 128 thr: mb=t>>4, nb=t&15
// NOTE: spatial rows are 126 floats -> only 8B alignment guaranteed; use float2 stores.
// ======================================================================
__global__ __launch_bounds__(128) void k_inv(const float* __restrict__ sb,
                                             const float* __restrict__ mb_) {
    extern __shared__ float sm[];
    float* As = sm;               // [128][68]
    float* Bs = sm + 128 * 68;    // [128][128]
    int bc = blockIdx.x, t = threadIdx.x;
    const float* src = g_s1 + (size_t)bc * 8192;
    for (int idx = t; idx < 8192; idx += 128) {
        int ri = idx >> 12, h = (idx >> 6) & 63, kx = idx & 63;
        As[(ri * 64 + kx) * 68 + h] = src[idx];
    }
    for (int idx = t; idx < 16384; idx += 128) Bs[idx] = g_invW[idx];
    __syncthreads();
    int mb = t >> 4, nb = t & 15;
    u64 acc[4][8];
#pragma unroll
    for (int r = 0; r < 4; r++)
#pragma unroll
        for (int c = 0; c < 8; c++) acc[r][c] = 0ull;
    const float* ap = As + mb * 8;
    const float* bp = Bs + nb * 8;
#pragma unroll 2
    for (int k = 0; k < 128; k++) GEMM_STEP(ap, bp, 68, 128, k)
    int ch = bc & 63;
    float bias = __ldg(sb + ch) + __ldg(mb_ + ch);
    int w0 = nb * 8;
    float* dst = g_x + (size_t)bc * HW_;
#pragma unroll
    for (int r = 0; r < 4; r++) {
        int h0 = mb * 8 + 2 * r;
        float vv[2][8];
#pragma unroll
        for (int c = 0; c < 8; c++) { vv[0][c] = lo32(acc[r][c]); vv[1][c] = hi32(acc[r][c]); }
#pragma unroll
        for (int p = 0; p < 2; p++) {
            float g[8];
#pragma unroll
            for (int c = 0; c < 8; c++) {
                float v = vv[p][c] + bias;
                g[c] = 0.5f * v * (1.0f + erff(v * 0.70710678118654752f));
            }
            // row offset = (h0+p)*126 + w0: always even -> 8B aligned. float2 only.
            float* row = dst + (h0 + p) * 126 + w0;
#pragma unroll
            for (int q = 0; q < 4; q++) {
                int w = w0 + 2 * q;
                if (w < 126)
                    *(float2*)(row + 2 * q) = make_float2(g[2 * q], g[2 * q + 1]);
            }
        }
    }
}

// ---------------- decoder 1x1 conv 64 -> 1 ----------------
__global__ __launch_bounds__(256) void k_dec(const float* __restrict__ dw,
                                             const float* __restrict__ db,
                                             float* __restrict__ out) {
    __shared__ float sw[64];
    int b = blockIdx.x, t = threadIdx.x;
    if (t < 64) sw[t] = dw[t];
    __syncthreads();
    float bias = __ldg(db);
    for (int p = t; p < HW_; p += 256) {
        float s = bias;
        const float* base = g_x + (size_t)b * 64 * HW_ + p;
#pragma unroll 8
        for (int c = 0; c < 64; c++) s = fmaf(sw[c], base[(size_t)c * HW_], s);
        out[(size_t)b * HW_ + p] = s;
    }
}

extern "C" void kernel_launch(void* const* d_in, const int* in_sizes, int n_in,
                              void* d_out, int out_size) {
    const float* x       = (const float*)d_in[0];
    const float* mode_w  = (const float*)d_in[1];
    const float* enc_w   = (const float*)d_in[2];
    const float* enc_b   = (const float*)d_in[3];
    const float* dec_w   = (const float*)d_in[4];
    const float* dec_b   = (const float*)d_in[5];
    const float* spec_w  = (const float*)d_in[6];
    const float* spec_b  = (const float*)d_in[7];
    const float* mlp_w   = (const float*)d_in[8];
    const float* mlp_b   = (const float*)d_in[9];
    float* out = (float*)d_out;

    const int smemF = (126 * 68 + 126 * 128) * 4;   // 98,784  -> 2 CTA/SM
    const int smemH = (128 * 132 + 128 * 64) * 4;   // 100,352 -> 2 CTA/SM
    const int smemG = (64 * 260 + 64 * 64) * 4;     // 82,944  -> 2 CTA/SM
    const int smemI = (128 * 68 + 128 * 128) * 4;   // 100,352 -> 2 CTA/SM
    cudaFuncSetAttribute(k_fwdW,  cudaFuncAttributeMaxDynamicSharedMemorySize, smemF);
    cudaFuncSetAttribute(k_hdft,  cudaFuncAttributeMaxDynamicSharedMemorySize, smemH);
    cudaFuncSetAttribute(k_sgemm, cudaFuncAttributeMaxDynamicSharedMemorySize, smemG);
    cudaFuncSetAttribute(k_inv,   cudaFuncAttributeMaxDynamicSharedMemorySize, smemI);

    k_basis<<<64, 256>>>(mode_w);
    k_enc<<<8192, 256>>>(x, enc_w, enc_b);

    for (int l = 0; l < 4; l++) {
        k_wt<<<dim3(128, 128), dim3(32, 8)>>>(spec_w + (size_t)l * 16777216,
                                              mlp_w + (size_t)l * 4096);
        k_fwdW<<<8192, 128, smemF>>>();
        k_hdft<<<8192, 128, smemH>>>(1);
        k_t1<<<8192, 256>>>();
        k_sgemm<<<4096, 256, smemG>>>();
        k_t2<<<8192, 256>>>();
        k_hdft<<<8192, 128, smemH>>>(0);
        k_inv<<<8192, 128, smemI>>>(spec_b + l * 64, mlp_b + l * 64);
    }
    k_dec<<<128, 256>>>(dec_w, dec_b, out);
}

// round 7
// speedup vs baseline: 2.5163x; 1.2096x over previous
#include <cuda_runtime.h>
#include <math.h>

#define HW_   8064          // 64*126
#define BC_   8192          // 128*64
#define NMODE 4096          // 64*64

typedef unsigned long long u64;

__device__ __forceinline__ float lo32(u64 v) { return __uint_as_float((unsigned)v); }
__device__ __forceinline__ float hi32(u64 v) { return __uint_as_float((unsigned)(v >> 32)); }
__device__ __forceinline__ void fma2(u64& d, u64 a, u64 b) {
    asm("fma.rn.f32x2 %0, %1, %2, %0;" : "+l"(d) : "l"(a), "l"(b));
}
__device__ __forceinline__ u64 pack2(float x) {
    u64 d; asm("mov.b64 %0, {%1, %1};" : "=l"(d) : "f"(x)); return d;
}

// ---------------- device scratch ----------------
__device__ __align__(16) float g_x  [BC_ * (size_t)HW_];
__device__ __align__(16) float g_s1 [BC_ * (size_t)8192];
__device__ __align__(16) float g_xf [BC_ * (size_t)8192];
__device__ __align__(16) float g_xfm[NMODE * (size_t)16384];
__device__ __align__(16) float g_wt [NMODE * (size_t)4096];
__device__ __align__(16) float g_fwdW[126 * 128];  // [w][n]
__device__ __align__(16) float g_invW[128 * 128];  // [n][w]
__device__ __align__(16) float g_Gt  [128 * 128];  // [j][m]
__device__ __align__(16) float g_G2t [128 * 128];  // [j][m]
__device__ __align__(16) float g_mw  [4096];

// ---------------- basis precompute ----------------
__global__ void k_basis(const float* __restrict__ mwin) {
    int i = blockIdx.x * blockDim.x + threadIdx.x;
    const double PI2 = 6.283185307179586476925286766559;
    if (i < 126 * 128) {
        int w = i / 128, n = i % 128, k = n & 63;
        double th = PI2 * (double)(k * w) / 126.0;
        g_fwdW[i] = (n < 64) ? (float)cos(th) : (float)(-sin(th));
    }
    if (i < 128 * 128) {
        int j = i / 128, w = i % 128;
        float v = 0.f;
        if (w < 126) {
            int k = j & 63;
            double a = (k == 0 || k == 63) ? (1.0 / 126.0) : (2.0 / 126.0);
            double th = PI2 * (double)(k * w) / 126.0;
            v = (j < 64) ? (float)(a * cos(th)) : (float)(-a * sin(th));
        }
        g_invW[i] = v;
    }
    if (i < 128 * 128) {
        int j = i / 128, m = i % 128;
        int ky = m & 63, h = j & 63;
        double th = PI2 * (double)(ky * h) / 64.0;
        double c = cos(th), s = sin(th);
        g_Gt[i] = (float)((m < 64) ? ((j < 64) ? c : s) : ((j < 64) ? -s : c));
    }
    if (i < 128 * 128) {
        int j = i / 128, m = i % 128;
        int h = m & 63, ky = j & 63;
        double th = PI2 * (double)(ky * h) / 64.0;
        double c = cos(th) / 64.0, s = sin(th) / 64.0;
        g_G2t[i] = (float)((m < 64) ? ((j < 64) ? c : -s) : ((j < 64) ? s : c));
    }
    if (i < 4096) {
        int ky = i >> 6, kx = i & 63;
        float s1 = 1.f / (1.f + expf(-mwin[i]));
        if (kx == 0 || kx == 63) {
            float s2 = 1.f / (1.f + expf(-mwin[(((64 - ky) & 63) << 6) + kx]));
            s1 = 0.5f * (s1 + s2);
        }
        g_mw[i] = s1;
    }
}

// ---------------- encoder 1x1 conv 3 -> 64 ----------------
__global__ __launch_bounds__(256) void k_enc(const float* __restrict__ xin,
                                             const float* __restrict__ ew,
                                             const float* __restrict__ eb) {
    __shared__ float sx[3 * 126];
    __shared__ float sw[192];
    __shared__ float sb[64];
    int b = blockIdx.x >> 6, h = blockIdx.x & 63;
    int t = threadIdx.x;
    if (t < 192) sw[t] = ew[t];
    if (t < 64)  sb[t] = eb[t];
    for (int idx = t; idx < 378; idx += 256) {
        int j = idx / 126, w = idx % 126;
        sx[idx] = xin[(size_t)(b * 3 + j) * HW_ + h * 126 + w];
    }
    __syncthreads();
    for (int idx = t; idx < 64 * 126; idx += 256) {
        int c = idx / 126, w = idx % 126;
        float v = sb[c] + sw[c * 3] * sx[w] + sw[c * 3 + 1] * sx[126 + w]
                        + sw[c * 3 + 2] * sx[252 + w];
        g_x[(size_t)(b * 64 + c) * HW_ + h * 126 + w] = v;
    }
}

// ======================================================================
// GEMM inner-loop macro: 8x8 tile, M-paired FFMA2
// ======================================================================
#define GEMM_STEP(ap, bp, SA, SB, kk)                                        \
    {                                                                        \
        ulonglong2 av0 = *(const ulonglong2*)((ap) + (kk) * (SA));           \
        ulonglong2 av1 = *(const ulonglong2*)((ap) + (kk) * (SA) + 4);       \
        u64 aa0 = av0.x, aa1 = av0.y, aa2 = av1.x, aa3 = av1.y;              \
        float4 b0 = *(const float4*)((bp) + (kk) * (SB));                    \
        float4 b1 = *(const float4*)((bp) + (kk) * (SB) + 4);                \
        u64 bb[8] = {pack2(b0.x), pack2(b0.y), pack2(b0.z), pack2(b0.w),     \
                     pack2(b1.x), pack2(b1.y), pack2(b1.z), pack2(b1.w)};    \
        _Pragma("unroll")                                                    \
        for (int c = 0; c < 8; c++) {                                        \
            fma2(acc[0][c], aa0, bb[c]);                                     \
            fma2(acc[1][c], aa1, bb[c]);                                     \
            fma2(acc[2][c], aa2, bb[c]);                                     \
            fma2(acc[3][c], aa3, bb[c]);                                     \
        }                                                                    \
    }

#define ZERO_ACC                                                             \
    u64 acc[4][8];                                                           \
    _Pragma("unroll")                                                        \
    for (int r = 0; r < 4; r++)                                              \
        _Pragma("unroll")                                                    \
        for (int c = 0; c < 8; c++) acc[r][c] = 0ull;

// ======================================================================
// forward width DFT: 256 thr, CTA = 128 global rows (2 bc) x 128 n, K=126 (2x63)
// As = x^T chunk [63 w][132], Bs = fwdW chunk [63][128]
// ======================================================================
__global__ __launch_bounds__(256) void k_fwdW() {
    extern __shared__ float sm[];
    float* As = sm;              // [63][132]
    float* Bs = sm + 63 * 132;   // [63][128]
    int t = threadIdx.x;
    size_t rowBase = (size_t)blockIdx.x * 128;
    const float* srcA = g_x + rowBase * 126;
    int mb = t >> 4, nb = t & 15;
    ZERO_ACC
    const float* ap = As + mb * 8;
    const float* bp = Bs + nb * 8;
#pragma unroll 1
    for (int chunk = 0; chunk < 2; chunk++) {
        int k0 = chunk * 63;
        for (int idx = t; idx < 128 * 63; idx += 256) {
            int m = idx / 63, w = idx - m * 63;
            As[w * 132 + m] = srcA[(size_t)m * 126 + k0 + w];
        }
        for (int idx = t; idx < 63 * 128; idx += 256)
            Bs[idx] = g_fwdW[k0 * 128 + idx];
        __syncthreads();
#pragma unroll 2
        for (int k = 0; k < 63; k++) GEMM_STEP(ap, bp, 132, 128, k)
        __syncthreads();
    }
    int ri = nb >> 3, kx0 = (nb & 7) * 8;
    int bc = blockIdx.x * 2 + (mb >> 3);
    int hb = (mb & 7) * 8;
    float* dst = g_s1 + (size_t)bc * 8192 + ri * 4096 + kx0;
#pragma unroll
    for (int r = 0; r < 4; r++) {
        int h0 = hb + 2 * r;
        float lo[8], hi[8];
#pragma unroll
        for (int c = 0; c < 8; c++) { lo[c] = lo32(acc[r][c]); hi[c] = hi32(acc[r][c]); }
        *(float4*)(dst + h0 * 64)           = make_float4(lo[0], lo[1], lo[2], lo[3]);
        *(float4*)(dst + h0 * 64 + 4)       = make_float4(lo[4], lo[5], lo[6], lo[7]);
        *(float4*)(dst + (h0 + 1) * 64)     = make_float4(hi[0], hi[1], hi[2], hi[3]);
        *(float4*)(dst + (h0 + 1) * 64 + 4) = make_float4(hi[4], hi[5], hi[6], hi[7]);
    }
}

// ======================================================================
// height transform: 256 thr, CTA = 128 m x 128 cols (2 bc x 64 kx), K=128 (2x64)
// As = basis^T chunk [64 j][132], Bs = S chunk [64 j][128 c]
// ======================================================================
__global__ __launch_bounds__(256) void k_hdft(int fwd) {
    extern __shared__ float sm[];
    float* As = sm;              // [64][132]
    float* Bs = sm + 64 * 132;   // [64][128]
    int t = threadIdx.x;
    int bcBase = blockIdx.x * 2;
    const float* basisT = fwd ? g_Gt : g_G2t;
    const float* in  = fwd ? g_s1 : g_xf;
    float*       out = fwd ? g_xf : g_s1;
    int mb = t >> 4, nb = t & 15;
    ZERO_ACC
    const float* ap = As + mb * 8;
    const float* bp = Bs + nb * 8;
#pragma unroll 1
    for (int chunk = 0; chunk < 2; chunk++) {
        int j0 = chunk * 64;
        for (int idx = t; idx < 64 * 128; idx += 256) {
            int j = idx >> 7, m = idx & 127;
            As[j * 132 + m] = basisT[(j0 + j) * 128 + m];
        }
        for (int idx = t; idx < 64 * 128; idx += 256) {
            int j = idx >> 7, c = idx & 127;
            Bs[idx] = in[(size_t)(bcBase + (c >> 6)) * 8192 + (j0 + j) * 64 + (c & 63)];
        }
        __syncthreads();
#pragma unroll 2
        for (int k = 0; k < 64; k++) GEMM_STEP(ap, bp, 132, 128, k)
        __syncthreads();
    }
    int c0 = nb * 8;
    int bc = bcBase + (c0 >> 6), kx0 = c0 & 63;
    float* dst = out + (size_t)bc * 8192 + kx0;
#pragma unroll
    for (int r = 0; r < 4; r++) {
        int m0 = mb * 8 + 2 * r;
        float lo[8], hi[8];
#pragma unroll
        for (int c = 0; c < 8; c++) { lo[c] = lo32(acc[r][c]); hi[c] = hi32(acc[r][c]); }
        if (fwd) {
            const float* w0 = g_mw + (m0 & 63) * 64 + kx0;
            const float* w1 = g_mw + ((m0 + 1) & 63) * 64 + kx0;
#pragma unroll
            for (int c = 0; c < 8; c++) { lo[c] *= w0[c]; hi[c] *= w1[c]; }
        }
        *(float4*)(dst + m0 * 64)           = make_float4(lo[0], lo[1], lo[2], lo[3]);
        *(float4*)(dst + m0 * 64 + 4)       = make_float4(lo[4], lo[5], lo[6], lo[7]);
        *(float4*)(dst + (m0 + 1) * 64)     = make_float4(hi[0], hi[1], hi[2], hi[3]);
        *(float4*)(dst + (m0 + 1) * 64 + 4) = make_float4(hi[4], hi[5], hi[6], hi[7]);
    }
}

// ---------------- transpose to mode-major ----------------
__global__ __launch_bounds__(256) void k_t1() {
    __shared__ float s[128 * 65];
    int b = blockIdx.x >> 6, ky = blockIdx.x & 63;
    int t = threadIdx.x;
    for (int idx = t; idx < 8192; idx += 256) {
        int i = idx >> 7, r = idx & 127, ri = r >> 6, kx = r & 63;
        s[(ri * 64 + i) * 65 + kx] =
            g_xf[(size_t)(b * 64 + i) * 8192 + ri * 4096 + ky * 64 + kx];
    }
    __syncthreads();
    for (int idx = t; idx < 8192; idx += 256) {
        int kx = idx >> 7, c = idx & 127;
        g_xfm[(size_t)(ky * 64 + kx) * 16384 + b * 128 + c] = s[c * 65 + kx];
    }
}

// ---------------- transpose back from mode-major ----------------
__global__ __launch_bounds__(256) void k_t2() {
    __shared__ float s[128 * 65];
    int b = blockIdx.x >> 6, ky = blockIdx.x & 63;
    int t = threadIdx.x;
    for (int idx = t; idx < 8192; idx += 256) {
        int kx = idx >> 7, c = idx & 127;
        s[c * 65 + kx] = g_s1[(size_t)(ky * 64 + kx) * 16384 + b * 128 + c];
    }
    __syncthreads();
    for (int idx = t; idx < 8192; idx += 256) {
        int o = idx >> 7, r = idx & 127, ri = r >> 6, kx = r & 63;
        g_xf[(size_t)(b * 64 + o) * 8192 + ri * 4096 + ky * 64 + kx] =
            s[(ri * 64 + o) * 65 + kx];
    }
}

// ---------------- weight fold ----------------
__global__ void k_wt(const float* __restrict__ spec, const float* __restrict__ mlp) {
    __shared__ float tile[32][33];
    int x = blockIdx.x * 32 + threadIdx.x;   // mode
    int yb = blockIdx.y * 32;                // io
#pragma unroll
    for (int j = 0; j < 32; j += 8)
        tile[threadIdx.y + j][threadIdx.x] = spec[(size_t)(yb + threadIdx.y + j) * 4096 + x];
    __syncthreads();
    int io2 = yb + threadIdx.x;
    float madd = mlp[(io2 & 63) * 64 + (io2 >> 6)];
    int mb = blockIdx.x * 32;
#pragma unroll
    for (int j = 0; j < 32; j += 8)
        g_wt[(size_t)(mb + threadIdx.y + j) * 4096 + io2] =
            tile[threadIdx.x][threadIdx.y + j] + madd;
}

// ======================================================================
// per-mode GEMM: C[256 x 64] = X[256 x 64] W[64 x 64], K=64
// As = X^T [64 i][260], Bs = W [64][64]. 256 thr: mb=t>>3 (32), nb=t&7
// ======================================================================
__global__ __launch_bounds__(256) void k_sgemm() {
    extern __shared__ float sm[];
    float* As = sm;             // [64][260]
    float* Bs = sm + 64 * 260;  // [64][64]
    int mode = blockIdx.x, t = threadIdx.x;
    const float* asrc = g_xfm + (size_t)mode * 16384;
    const float* wsrc = g_wt + (size_t)mode * 4096;
    for (int idx = t; idx < 16384; idx += 256) {
        int row = idx >> 6, i = idx & 63;
        As[i * 260 + row] = asrc[idx];
    }
    for (int idx = t; idx < 4096; idx += 256) Bs[idx] = wsrc[idx];
    __syncthreads();
    int mb = t >> 3, nb = t & 7;
    ZERO_ACC
    const float* ap = As + mb * 8;
    const float* bp = Bs + nb * 8;
#pragma unroll 2
    for (int k = 0; k < 64; k++) GEMM_STEP(ap, bp, 260, 64, k)
    int o0 = nb * 8;
    float* dst = g_s1 + (size_t)mode * 16384 + o0;
#pragma unroll
    for (int r = 0; r < 4; r++) {
        int row0 = mb * 8 + 2 * r;
        float lo[8], hi[8];
#pragma unroll
        for (int c = 0; c < 8; c++) { lo[c] = lo32(acc[r][c]); hi[c] = hi32(acc[r][c]); }
        *(float4*)(dst + row0 * 64)           = make_float4(lo[0], lo[1], lo[2], lo[3]);
        *(float4*)(dst + row0 * 64 + 4)       = make_float4(lo[4], lo[5], lo[6], lo[7]);
        *(float4*)(dst + (row0 + 1) * 64)     = make_float4(hi[0], hi[1], hi[2], hi[3]);
        *(float4*)(dst + (row0 + 1) * 64 + 4) = make_float4(hi[4], hi[5], hi[6], hi[7]);
    }
}

// ======================================================================
// inverse width + bias + exact GELU: 256 thr, CTA = 128 rows (2 bc) x 126 w, K=128 (2x64)
// As = U^T chunk [64 n][132], Bs = invW chunk [64][128]
// float2 stores only (spatial row stride 126 -> 8B alignment)
// ======================================================================
__global__ __launch_bounds__(256) void k_inv(const float* __restrict__ sb,
                                             const float* __restrict__ mb_) {
    extern __shared__ float sm[];
    float* As = sm;              // [64][132]
    float* Bs = sm + 64 * 132;   // [64][128]
    int t = threadIdx.x;
    int bcBase = blockIdx.x * 2;
    int mb = t >> 4, nb = t & 15;
    ZERO_ACC
    const float* ap = As + mb * 8;
    const float* bp = Bs + nb * 8;
#pragma unroll 1
    for (int chunk = 0; chunk < 2; chunk++) {
        int n0 = chunk * 64;           // n = ri*64+kx ; this chunk: ri = chunk, kx = nn
        for (int idx = t; idx < 64 * 128; idx += 256) {
            int m = idx >> 6, nn = idx & 63;
            int bc = bcBase + (m >> 6), h = m & 63;
            As[nn * 132 + m] = g_s1[(size_t)bc * 8192 + chunk * 4096 + h * 64 + nn];
        }
        for (int idx = t; idx < 64 * 128; idx += 256)
            Bs[idx] = g_invW[n0 * 128 + idx];
        __syncthreads();
#pragma unroll 2
        for (int k = 0; k < 64; k++) GEMM_STEP(ap, bp, 132, 128, k)
        __syncthreads();
    }
    int bc = bcBase + (mb >> 3);
    int hb = (mb & 7) * 8;
    int ch = bc & 63;
    float bias = __ldg(sb + ch) + __ldg(mb_ + ch);
    int w0 = nb * 8;
    float* dst = g_x + (size_t)bc * HW_;
#pragma unroll
    for (int r = 0; r < 4; r++) {
        int h0 = hb + 2 * r;
        float vv[2][8];
#pragma unroll
        for (int c = 0; c < 8; c++) { vv[0][c] = lo32(acc[r][c]); vv[1][c] = hi32(acc[r][c]); }
#pragma unroll
        for (int p = 0; p < 2; p++) {
            float g[8];
#pragma unroll
            for (int c = 0; c < 8; c++) {
                float v = vv[p][c] + bias;
                g[c] = 0.5f * v * (1.0f + erff(v * 0.70710678118654752f));
            }
            float* row = dst + (h0 + p) * 126 + w0;
#pragma unroll
            for (int q = 0; q < 4; q++) {
                int w = w0 + 2 * q;
                if (w < 126)
                    *(float2*)(row + 2 * q) = make_float2(g[2 * q], g[2 * q + 1]);
            }
        }
    }
}

// ---------------- decoder 1x1 conv 64 -> 1 ----------------
__global__ __launch_bounds__(256) void k_dec(const float* __restrict__ dw,
                                             const float* __restrict__ db,
                                             float* __restrict__ out) {
    __shared__ float sw[64];
    int b = blockIdx.x, t = threadIdx.x;
    if (t < 64) sw[t] = dw[t];
    __syncthreads();
    float bias = __ldg(db);
    for (int p = t; p < HW_; p += 256) {
        float s = bias;
        const float* base = g_x + (size_t)b * 64 * HW_ + p;
#pragma unroll 8
        for (int c = 0; c < 64; c++) s = fmaf(sw[c], base[(size_t)c * HW_], s);
        out[(size_t)b * HW_ + p] = s;
    }
}

extern "C" void kernel_launch(void* const* d_in, const int* in_sizes, int n_in,
                              void* d_out, int out_size) {
    const float* x       = (const float*)d_in[0];
    const float* mode_w  = (const float*)d_in[1];
    const float* enc_w   = (const float*)d_in[2];
    const float* enc_b   = (const float*)d_in[3];
    const float* dec_w   = (const float*)d_in[4];
    const float* dec_b   = (const float*)d_in[5];
    const float* spec_w  = (const float*)d_in[6];
    const float* spec_b  = (const float*)d_in[7];
    const float* mlp_w   = (const float*)d_in[8];
    const float* mlp_b   = (const float*)d_in[9];
    float* out = (float*)d_out;

    const int smemF = (63 * 132 + 63 * 128) * 4;    // 65,520  -> 2 CTA/SM (reg-limited)
    const int smemH = (64 * 132 + 64 * 128) * 4;    // 66,560
    const int smemG = (64 * 260 + 64 * 64) * 4;     // 82,944
    const int smemI = (64 * 132 + 64 * 128) * 4;    // 66,560
    cudaFuncSetAttribute(k_fwdW,  cudaFuncAttributeMaxDynamicSharedMemorySize, smemF);
    cudaFuncSetAttribute(k_hdft,  cudaFuncAttributeMaxDynamicSharedMemorySize, smemH);
    cudaFuncSetAttribute(k_sgemm, cudaFuncAttributeMaxDynamicSharedMemorySize, smemG);
    cudaFuncSetAttribute(k_inv,   cudaFuncAttributeMaxDynamicSharedMemorySize, smemI);

    k_basis<<<64, 256>>>(mode_w);
    k_enc<<<8192, 256>>>(x, enc_w, enc_b);

    for (int l = 0; l < 4; l++) {
        k_wt<<<dim3(128, 128), dim3(32, 8)>>>(spec_w + (size_t)l * 16777216,
                                              mlp_w + (size_t)l * 4096);
        k_fwdW<<<4096, 256, smemF>>>();
        k_hdft<<<4096, 256, smemH>>>(1);
        k_t1<<<8192, 256>>>();
        k_sgemm<<<4096, 256, smemG>>>();
        k_t2<<<8192, 256>>>();
        k_hdft<<<4096, 256, smemH>>>(0);
        k_inv<<<4096, 256, smemI>>>(spec_b + l * 64, mlp_b + l * 64);
    }
    k_dec<<<128, 256>>>(dec_w, dec_b, out);
}

// round 8
// speedup vs baseline: 2.5496x; 1.0132x over previous
#include <cuda_runtime.h>
#include <math.h>

#define HW_   8064          // 64*126
#define BC_   8192          // 128*64
#define NMODE 4096          // 64*64

typedef unsigned long long u64;

__device__ __forceinline__ float lo32(u64 v) { return __uint_as_float((unsigned)v); }
__device__ __forceinline__ float hi32(u64 v) { return __uint_as_float((unsigned)(v >> 32)); }
__device__ __forceinline__ void fma2(u64& d, u64 a, u64 b) {
    asm("fma.rn.f32x2 %0, %1, %2, %0;" : "+l"(d) : "l"(a), "l"(b));
}
__device__ __forceinline__ u64 pack2(float x) {
    u64 d; asm("mov.b64 %0, {%1, %1};" : "=l"(d) : "f"(x)); return d;
}

// ---------------- device scratch ----------------
__device__ __align__(16) float g_x  [BC_ * (size_t)HW_];
__device__ __align__(16) float g_s1 [BC_ * (size_t)8192];
__device__ __align__(16) float g_xf [BC_ * (size_t)8192];
__device__ __align__(16) float g_xfm[NMODE * (size_t)16384];
__device__ __align__(16) float g_wt [NMODE * (size_t)4096];
__device__ __align__(16) float g_fwdW[126 * 128];  // [w][n]
__device__ __align__(16) float g_invW[128 * 128];  // [n][w]
__device__ __align__(16) float g_Gt  [128 * 128];  // [j][m]
__device__ __align__(16) float g_G2t [128 * 128];  // [j][m]
__device__ __align__(16) float g_mw  [4096];

// ---------------- basis precompute ----------------
__global__ void k_basis(const float* __restrict__ mwin) {
    int i = blockIdx.x * blockDim.x + threadIdx.x;
    const double PI2 = 6.283185307179586476925286766559;
    if (i < 126 * 128) {
        int w = i / 128, n = i % 128, k = n & 63;
        double th = PI2 * (double)(k * w) / 126.0;
        g_fwdW[i] = (n < 64) ? (float)cos(th) : (float)(-sin(th));
    }
    if (i < 128 * 128) {
        int j = i / 128, w = i % 128;
        float v = 0.f;
        if (w < 126) {
            int k = j & 63;
            double a = (k == 0 || k == 63) ? (1.0 / 126.0) : (2.0 / 126.0);
            double th = PI2 * (double)(k * w) / 126.0;
            v = (j < 64) ? (float)(a * cos(th)) : (float)(-a * sin(th));
        }
        g_invW[i] = v;
    }
    if (i < 128 * 128) {
        int j = i / 128, m = i % 128;
        int ky = m & 63, h = j & 63;
        double th = PI2 * (double)(ky * h) / 64.0;
        double c = cos(th), s = sin(th);
        g_Gt[i] = (float)((m < 64) ? ((j < 64) ? c : s) : ((j < 64) ? -s : c));
    }
    if (i < 128 * 128) {
        int j = i / 128, m = i % 128;
        int h = m & 63, ky = j & 63;
        double th = PI2 * (double)(ky * h) / 64.0;
        double c = cos(th) / 64.0, s = sin(th) / 64.0;
        g_G2t[i] = (float)((m < 64) ? ((j < 64) ? c : -s) : ((j < 64) ? s : c));
    }
    if (i < 4096) {
        int ky = i >> 6, kx = i & 63;
        float s1 = 1.f / (1.f + expf(-mwin[i]));
        if (kx == 0 || kx == 63) {
            float s2 = 1.f / (1.f + expf(-mwin[(((64 - ky) & 63) << 6) + kx]));
            s1 = 0.5f * (s1 + s2);
        }
        g_mw[i] = s1;
    }
}

// ---------------- encoder 1x1 conv 3 -> 64 ----------------
__global__ __launch_bounds__(256) void k_enc(const float* __restrict__ xin,
                                             const float* __restrict__ ew,
                                             const float* __restrict__ eb) {
    __shared__ float sx[3 * 126];
    __shared__ float sw[192];
    __shared__ float sb[64];
    int b = blockIdx.x >> 6, h = blockIdx.x & 63;
    int t = threadIdx.x;
    if (t < 192) sw[t] = ew[t];
    if (t < 64)  sb[t] = eb[t];
    for (int idx = t; idx < 378; idx += 256) {
        int j = idx / 126, w = idx % 126;
        sx[idx] = xin[(size_t)(b * 3 + j) * HW_ + h * 126 + w];
    }
    __syncthreads();
    for (int idx = t; idx < 64 * 126; idx += 256) {
        int c = idx / 126, w = idx % 126;
        float v = sb[c] + sw[c * 3] * sx[w] + sw[c * 3 + 1] * sx[126 + w]
                        + sw[c * 3 + 2] * sx[252 + w];
        g_x[(size_t)(b * 64 + c) * HW_ + h * 126 + w] = v;
    }
}

// ======================================================================
// Software-pipelined GEMM core: 8x8 tile, M-paired FFMA2, K=64, dbl-buffered
// ======================================================================
#define DECL_ACC                                                             \
    u64 acc[4][8];                                                           \
    _Pragma("unroll")                                                        \
    for (int r = 0; r < 4; r++)                                              \
        _Pragma("unroll")                                                    \
        for (int c = 0; c < 8; c++) acc[r][c] = 0ull;

#define DECL_PIPE ulonglong2 pa0[2], pa1[2]; float4 pb0[2], pb1[2];

#define LOADF(buf, kk)                                                       \
    pa0[buf] = *(const ulonglong2*)(ap + (kk) * SA);                         \
    pa1[buf] = *(const ulonglong2*)(ap + (kk) * SA + 4);                     \
    pb0[buf] = *(const float4*)(bp + (kk) * SB);                             \
    pb1[buf] = *(const float4*)(bp + (kk) * SB + 4);

#define COMPUTEF(buf)                                                        \
    {                                                                        \
        u64 aa0 = pa0[buf].x, aa1 = pa0[buf].y;                              \
        u64 aa2 = pa1[buf].x, aa3 = pa1[buf].y;                              \
        u64 bb[8] = {pack2(pb0[buf].x), pack2(pb0[buf].y),                   \
                     pack2(pb0[buf].z), pack2(pb0[buf].w),                   \
                     pack2(pb1[buf].x), pack2(pb1[buf].y),                   \
                     pack2(pb1[buf].z), pack2(pb1[buf].w)};                  \
        _Pragma("unroll")                                                    \
        for (int c = 0; c < 8; c++) {                                        \
            fma2(acc[0][c], aa0, bb[c]);                                     \
            fma2(acc[1][c], aa1, bb[c]);                                     \
            fma2(acc[2][c], aa2, bb[c]);                                     \
            fma2(acc[3][c], aa3, bb[c]);                                     \
        }                                                                    \
    }

// K = 64, even: steady-state 2-deep rotation, fixed epilogue
#define GEMM_PIPE64                                                          \
    LOADF(0, 0)                                                              \
    _Pragma("unroll 1")                                                      \
    for (int k = 0; k < 62; k += 2) {                                        \
        LOADF(1, k + 1)                                                      \
        COMPUTEF(0)                                                          \
        LOADF(0, k + 2)                                                      \
        COMPUTEF(1)                                                          \
    }                                                                        \
    LOADF(1, 63)                                                             \
    COMPUTEF(0)                                                              \
    COMPUTEF(1)

// ======================================================================
// forward width DFT: 256 thr, CTA = 128 global rows (2 bc) x 128 n
// K=126 as 2 chunks of 63, zero-padded to 64. As [64][132], Bs [64][128]
// ======================================================================
__global__ __launch_bounds__(256, 2) void k_fwdW() {
    extern __shared__ float sm[];
    float* As = sm;              // [64][132]
    float* Bs = sm + 64 * 132;   // [64][128]
    int t = threadIdx.x;
    size_t rowBase = (size_t)blockIdx.x * 128;
    const float* srcA = g_x + rowBase * 126;
    int mb = t >> 4, nb = t & 15;
    DECL_ACC
    DECL_PIPE
    const float* ap = As + mb * 8;
    const float* bp = Bs + nb * 8;
    const int SA = 132, SB = 128;
    // zero pad row k=63 once (never overwritten by staging below)
    for (int idx = t; idx < 132; idx += 256) As[63 * 132 + idx] = 0.f;
    for (int idx = t; idx < 128; idx += 256) Bs[63 * 128 + idx] = 0.f;
#pragma unroll 1
    for (int chunk = 0; chunk < 2; chunk++) {
        int k0 = chunk * 63;
        for (int idx = t; idx < 128 * 63; idx += 256) {
            int m = idx / 63, w = idx - m * 63;
            As[w * 132 + m] = srcA[(size_t)m * 126 + k0 + w];
        }
        for (int idx = t; idx < 63 * 128; idx += 256)
            Bs[idx] = g_fwdW[k0 * 128 + idx];
        __syncthreads();
        GEMM_PIPE64
        __syncthreads();
    }
    int ri = nb >> 3, kx0 = (nb & 7) * 8;
    int bc = blockIdx.x * 2 + (mb >> 3);
    int hb = (mb & 7) * 8;
    float* dst = g_s1 + (size_t)bc * 8192 + ri * 4096 + kx0;
#pragma unroll
    for (int r = 0; r < 4; r++) {
        int h0 = hb + 2 * r;
        float lo[8], hi[8];
#pragma unroll
        for (int c = 0; c < 8; c++) { lo[c] = lo32(acc[r][c]); hi[c] = hi32(acc[r][c]); }
        *(float4*)(dst + h0 * 64)           = make_float4(lo[0], lo[1], lo[2], lo[3]);
        *(float4*)(dst + h0 * 64 + 4)       = make_float4(lo[4], lo[5], lo[6], lo[7]);
        *(float4*)(dst + (h0 + 1) * 64)     = make_float4(hi[0], hi[1], hi[2], hi[3]);
        *(float4*)(dst + (h0 + 1) * 64 + 4) = make_float4(hi[4], hi[5], hi[6], hi[7]);
    }
}

// ======================================================================
// height transform: 256 thr, CTA = 128 m x 128 cols (2 bc x 64 kx), K=128 (2x64)
// ======================================================================
__global__ __launch_bounds__(256, 2) void k_hdft(int fwd) {
    extern __shared__ float sm[];
    float* As = sm;              // [64][132]
    float* Bs = sm + 64 * 132;   // [64][128]
    int t = threadIdx.x;
    int bcBase = blockIdx.x * 2;
    const float* basisT = fwd ? g_Gt : g_G2t;
    const float* in  = fwd ? g_s1 : g_xf;
    float*       out = fwd ? g_xf : g_s1;
    int mb = t >> 4, nb = t & 15;
    DECL_ACC
    DECL_PIPE
    const float* ap = As + mb * 8;
    const float* bp = Bs + nb * 8;
    const int SA = 132, SB = 128;
#pragma unroll 1
    for (int chunk = 0; chunk < 2; chunk++) {
        int j0 = chunk * 64;
        for (int idx = t; idx < 64 * 128; idx += 256) {
            int j = idx >> 7, m = idx & 127;
            As[j * 132 + m] = basisT[(j0 + j) * 128 + m];
        }
        for (int idx = t; idx < 64 * 128; idx += 256) {
            int j = idx >> 7, c = idx & 127;
            Bs[idx] = in[(size_t)(bcBase + (c >> 6)) * 8192 + (j0 + j) * 64 + (c & 63)];
        }
        __syncthreads();
        GEMM_PIPE64
        __syncthreads();
    }
    int c0 = nb * 8;
    int bc = bcBase + (c0 >> 6), kx0 = c0 & 63;
    float* dst = out + (size_t)bc * 8192 + kx0;
#pragma unroll
    for (int r = 0; r < 4; r++) {
        int m0 = mb * 8 + 2 * r;
        float lo[8], hi[8];
#pragma unroll
        for (int c = 0; c < 8; c++) { lo[c] = lo32(acc[r][c]); hi[c] = hi32(acc[r][c]); }
        if (fwd) {
            const float* w0 = g_mw + (m0 & 63) * 64 + kx0;
            const float* w1 = g_mw + ((m0 + 1) & 63) * 64 + kx0;
#pragma unroll
            for (int c = 0; c < 8; c++) { lo[c] *= w0[c]; hi[c] *= w1[c]; }
        }
        *(float4*)(dst + m0 * 64)           = make_float4(lo[0], lo[1], lo[2], lo[3]);
        *(float4*)(dst + m0 * 64 + 4)       = make_float4(lo[4], lo[5], lo[6], lo[7]);
        *(float4*)(dst + (m0 + 1) * 64)     = make_float4(hi[0], hi[1], hi[2], hi[3]);
        *(float4*)(dst + (m0 + 1) * 64 + 4) = make_float4(hi[4], hi[5], hi[6], hi[7]);
    }
}

// ---------------- transpose to mode-major ----------------
__global__ __launch_bounds__(256) void k_t1() {
    __shared__ float s[128 * 65];
    int b = blockIdx.x >> 6, ky = blockIdx.x & 63;
    int t = threadIdx.x;
    for (int idx = t; idx < 8192; idx += 256) {
        int i = idx >> 7, r = idx & 127, ri = r >> 6, kx = r & 63;
        s[(ri * 64 + i) * 65 + kx] =
            g_xf[(size_t)(b * 64 + i) * 8192 + ri * 4096 + ky * 64 + kx];
    }
    __syncthreads();
    for (int idx = t; idx < 8192; idx += 256) {
        int kx = idx >> 7, c = idx & 127;
        g_xfm[(size_t)(ky * 64 + kx) * 16384 + b * 128 + c] = s[c * 65 + kx];
    }
}

// ---------------- transpose back from mode-major ----------------
__global__ __launch_bounds__(256) void k_t2() {
    __shared__ float s[128 * 65];
    int b = blockIdx.x >> 6, ky = blockIdx.x & 63;
    int t = threadIdx.x;
    for (int idx = t; idx < 8192; idx += 256) {
        int kx = idx >> 7, c = idx & 127;
        s[c * 65 + kx] = g_s1[(size_t)(ky * 64 + kx) * 16384 + b * 128 + c];
    }
    __syncthreads();
    for (int idx = t; idx < 8192; idx += 256) {
        int o = idx >> 7, r = idx & 127, ri = r >> 6, kx = r & 63;
        g_xf[(size_t)(b * 64 + o) * 8192 + ri * 4096 + ky * 64 + kx] =
            s[(ri * 64 + o) * 65 + kx];
    }
}

// ---------------- weight fold ----------------
__global__ void k_wt(const float* __restrict__ spec, const float* __restrict__ mlp) {
    __shared__ float tile[32][33];
    int x = blockIdx.x * 32 + threadIdx.x;   // mode
    int yb = blockIdx.y * 32;                // io
#pragma unroll
    for (int j = 0; j < 32; j += 8)
        tile[threadIdx.y + j][threadIdx.x] = spec[(size_t)(yb + threadIdx.y + j) * 4096 + x];
    __syncthreads();
    int io2 = yb + threadIdx.x;
    float madd = mlp[(io2 & 63) * 64 + (io2 >> 6)];
    int mb = blockIdx.x * 32;
#pragma unroll
    for (int j = 0; j < 32; j += 8)
        g_wt[(size_t)(mb + threadIdx.y + j) * 4096 + io2] =
            tile[threadIdx.x][threadIdx.y + j] + madd;
}

// ======================================================================
// per-mode GEMM: C[256 x 64] = X[256 x 64] W[64 x 64], K=64
// As = X^T [64 i][260], Bs = W [64][64]. 256 thr: mb=t>>3 (32), nb=t&7
// ======================================================================
__global__ __launch_bounds__(256, 2) void k_sgemm() {
    extern __shared__ float sm[];
    float* As = sm;             // [64][260]
    float* Bs = sm + 64 * 260;  // [64][64]
    int mode = blockIdx.x, t = threadIdx.x;
    const float* asrc = g_xfm + (size_t)mode * 16384;
    const float* wsrc = g_wt + (size_t)mode * 4096;
    for (int idx = t; idx < 16384; idx += 256) {
        int row = idx >> 6, i = idx & 63;
        As[i * 260 + row] = asrc[idx];
    }
    for (int idx = t; idx < 4096; idx += 256) Bs[idx] = wsrc[idx];
    __syncthreads();
    int mb = t >> 3, nb = t & 7;
    DECL_ACC
    DECL_PIPE
    const float* ap = As + mb * 8;
    const float* bp = Bs + nb * 8;
    const int SA = 260, SB = 64;
    GEMM_PIPE64
    int o0 = nb * 8;
    float* dst = g_s1 + (size_t)mode * 16384 + o0;
#pragma unroll
    for (int r = 0; r < 4; r++) {
        int row0 = mb * 8 + 2 * r;
        float lo[8], hi[8];
#pragma unroll
        for (int c = 0; c < 8; c++) { lo[c] = lo32(acc[r][c]); hi[c] = hi32(acc[r][c]); }
        *(float4*)(dst + row0 * 64)           = make_float4(lo[0], lo[1], lo[2], lo[3]);
        *(float4*)(dst + row0 * 64 + 4)       = make_float4(lo[4], lo[5], lo[6], lo[7]);
        *(float4*)(dst + (row0 + 1) * 64)     = make_float4(hi[0], hi[1], hi[2], hi[3]);
        *(float4*)(dst + (row0 + 1) * 64 + 4) = make_float4(hi[4], hi[5], hi[6], hi[7]);
    }
}

// ======================================================================
// inverse width + bias + exact GELU: 256 thr, CTA = 128 rows (2 bc), K=128 (2x64)
// float2 stores only (spatial row stride 126 -> 8B alignment)
// ======================================================================
__global__ __launch_bounds__(256, 2) void k_inv(const float* __restrict__ sb,
                                                const float* __restrict__ mb_) {
    extern __shared__ float sm[];
    float* As = sm;              // [64][132]
    float* Bs = sm + 64 * 132;   // [64][128]
    int t = threadIdx.x;
    int bcBase = blockIdx.x * 2;
    int mb = t >> 4, nb = t & 15;
    DECL_ACC
    DECL_PIPE
    const float* ap = As + mb * 8;
    const float* bp = Bs + nb * 8;
    const int SA = 132, SB = 128;
#pragma unroll 1
    for (int chunk = 0; chunk < 2; chunk++) {
        int n0 = chunk * 64;
        for (int idx = t; idx < 64 * 128; idx += 256) {
            int m = idx >> 6, nn = idx & 63;
            int bc = bcBase + (m >> 6), h = m & 63;
            As[nn * 132 + m] = g_s1[(size_t)bc * 8192 + chunk * 4096 + h * 64 + nn];
        }
        for (int idx = t; idx < 64 * 128; idx += 256)
            Bs[idx] = g_invW[n0 * 128 + idx];
        __syncthreads();
        GEMM_PIPE64
        __syncthreads();
    }
    int bc = bcBase + (mb >> 3);
    int hb = (mb & 7) * 8;
    int ch = bc & 63;
    float bias = __ldg(sb + ch) + __ldg(mb_ + ch);
    int w0 = nb * 8;
    float* dst = g_x + (size_t)bc * HW_;
#pragma unroll
    for (int r = 0; r < 4; r++) {
        int h0 = hb + 2 * r;
        float vv[2][8];
#pragma unroll
        for (int c = 0; c < 8; c++) { vv[0][c] = lo32(acc[r][c]); vv[1][c] = hi32(acc[r][c]); }
#pragma unroll
        for (int p = 0; p < 2; p++) {
            float g[8];
#pragma unroll
            for (int c = 0; c < 8; c++) {
                float v = vv[p][c] + bias;
                g[c] = 0.5f * v * (1.0f + erff(v * 0.70710678118654752f));
            }
            float* row = dst + (h0 + p) * 126 + w0;
#pragma unroll
            for (int q = 0; q < 4; q++) {
                int w = w0 + 2 * q;
                if (w < 126)
                    *(float2*)(row + 2 * q) = make_float2(g[2 * q], g[2 * q + 1]);
            }
        }
    }
}

// ---------------- decoder 1x1 conv 64 -> 1 ----------------
__global__ __launch_bounds__(256) void k_dec(const float* __restrict__ dw,
                                             const float* __restrict__ db,
                                             float* __restrict__ out) {
    __shared__ float sw[64];
    int b = blockIdx.x, t = threadIdx.x;
    if (t < 64) sw[t] = dw[t];
    __syncthreads();
    float bias = __ldg(db);
    for (int p = t; p < HW_; p += 256) {
        float s = bias;
        const float* base = g_x + (size_t)b * 64 * HW_ + p;
#pragma unroll 8
        for (int c = 0; c < 64; c++) s = fmaf(sw[c], base[(size_t)c * HW_], s);
        out[(size_t)b * HW_ + p] = s;
    }
}

extern "C" void kernel_launch(void* const* d_in, const int* in_sizes, int n_in,
                              void* d_out, int out_size) {
    const float* x       = (const float*)d_in[0];
    const float* mode_w  = (const float*)d_in[1];
    const float* enc_w   = (const float*)d_in[2];
    const float* enc_b   = (const float*)d_in[3];
    const float* dec_w   = (const float*)d_in[4];
    const float* dec_b   = (const float*)d_in[5];
    const float* spec_w  = (const float*)d_in[6];
    const float* spec_b  = (const float*)d_in[7];
    const float* mlp_w   = (const float*)d_in[8];
    const float* mlp_b   = (const float*)d_in[9];
    float* out = (float*)d_out;

    const int smemF = (64 * 132 + 64 * 128) * 4;    // 66,560 -> 2 CTA/SM
    const int smemH = (64 * 132 + 64 * 128) * 4;    // 66,560
    const int smemG = (64 * 260 + 64 * 64) * 4;     // 82,944
    const int smemI = (64 * 132 + 64 * 128) * 4;    // 66,560
    cudaFuncSetAttribute(k_fwdW,  cudaFuncAttributeMaxDynamicSharedMemorySize, smemF);
    cudaFuncSetAttribute(k_hdft,  cudaFuncAttributeMaxDynamicSharedMemorySize, smemH);
    cudaFuncSetAttribute(k_sgemm, cudaFuncAttributeMaxDynamicSharedMemorySize, smemG);
    cudaFuncSetAttribute(k_inv,   cudaFuncAttributeMaxDynamicSharedMemorySize, smemI);

    k_basis<<<64, 256>>>(mode_w);
    k_enc<<<8192, 256>>>(x, enc_w, enc_b);

    for (int l = 0; l < 4; l++) {
        k_wt<<<dim3(128, 128), dim3(32, 8)>>>(spec_w + (size_t)l * 16777216,
                                              mlp_w + (size_t)l * 4096);
        k_fwdW<<<4096, 256, smemF>>>();
        k_hdft<<<4096, 256, smemH>>>(1);
        k_t1<<<8192, 256>>>();
        k_sgemm<<<4096, 256, smemG>>>();
        k_t2<<<8192, 256>>>();
        k_hdft<<<4096, 256, smemH>>>(0);
        k_inv<<<4096, 256, smemI>>>(spec_b + l * 64, mlp_b + l * 64);
    }
    k_dec<<<128, 256>>>(dec_w, dec_b, out);
}

// round 9
// speedup vs baseline: 4.0203x; 1.5769x over previous
#include <cuda_runtime.h>
#include <cuda_bf16.h>
#include <math.h>
#include <stdint.h>

#define HW_   8064          // 64*126
#define BC_   8192          // 128*64
#define NMODE 4096          // 64*64

typedef __nv_bfloat16 bf16;

// ---------------- device scratch ----------------
__device__ __align__(16) float g_x  [BC_ * (size_t)HW_];
__device__ __align__(16) float g_s1 [BC_ * (size_t)8192];
__device__ __align__(16) float g_xf [BC_ * (size_t)8192];
__device__ __align__(16) float g_xfm[NMODE * (size_t)16384];
__device__ __align__(16) float g_wt [NMODE * (size_t)4096];
__device__ __align__(16) float g_fwdW[126 * 128];  // [w][n]
__device__ __align__(16) float g_invW[128 * 128];  // [n][w]
__device__ __align__(16) float g_Gf  [128 * 128];  // [m][j]  fwd height basis
__device__ __align__(16) float g_G2f [128 * 128];  // [m][j]  inv height basis
__device__ __align__(16) float g_mw  [4096];

// ---------------- basis precompute ----------------
__global__ void k_basis(const float* __restrict__ mwin) {
    int i = blockIdx.x * blockDim.x + threadIdx.x;
    const double PI2 = 6.283185307179586476925286766559;
    if (i < 126 * 128) {
        int w = i / 128, n = i % 128, k = n & 63;
        double th = PI2 * (double)(k * w) / 126.0;
        g_fwdW[i] = (n < 64) ? (float)cos(th) : (float)(-sin(th));
    }
    if (i < 128 * 128) {
        int j = i / 128, w = i % 128;
        float v = 0.f;
        if (w < 126) {
            int k = j & 63;
            double a = (k == 0 || k == 63) ? (1.0 / 126.0) : (2.0 / 126.0);
            double th = PI2 * (double)(k * w) / 126.0;
            v = (j < 64) ? (float)(a * cos(th)) : (float)(-a * sin(th));
        }
        g_invW[i] = v;
    }
    if (i < 128 * 128) {
        // g_Gf[m][j]: forward height DFT, C[m] = sum_j G[m][j] S[j]
        int m = i / 128, j = i % 128;
        int ky = m & 63, h = j & 63;
        double th = PI2 * (double)(ky * h) / 64.0;
        double c = cos(th), s = sin(th);
        g_Gf[i] = (float)((m < 64) ? ((j < 64) ? c : s) : ((j < 64) ? -s : c));
    }
    if (i < 128 * 128) {
        // g_G2f[m][j]: inverse height DFT (with 1/64)
        int m = i / 128, j = i % 128;
        int h = m & 63, ky = j & 63;
        double th = PI2 * (double)(ky * h) / 64.0;
        double c = cos(th) / 64.0, s = sin(th) / 64.0;
        g_G2f[i] = (float)((m < 64) ? ((j < 64) ? c : -s) : ((j < 64) ? s : c));
    }
    if (i < 4096) {
        int ky = i >> 6, kx = i & 63;
        float s1 = 1.f / (1.f + expf(-mwin[i]));
        if (kx == 0 || kx == 63) {
            float s2 = 1.f / (1.f + expf(-mwin[(((64 - ky) & 63) << 6) + kx]));
            s1 = 0.5f * (s1 + s2);
        }
        g_mw[i] = s1;
    }
}

// ---------------- encoder 1x1 conv 3 -> 64 ----------------
__global__ __launch_bounds__(256) void k_enc(const float* __restrict__ xin,
                                             const float* __restrict__ ew,
                                             const float* __restrict__ eb) {
    __shared__ float sx[3 * 126];
    __shared__ float sw[192];
    __shared__ float sb[64];
    int b = blockIdx.x >> 6, h = blockIdx.x & 63;
    int t = threadIdx.x;
    if (t < 192) sw[t] = ew[t];
    if (t < 64)  sb[t] = eb[t];
    for (int idx = t; idx < 378; idx += 256) {
        int j = idx / 126, w = idx % 126;
        sx[idx] = xin[(size_t)(b * 3 + j) * HW_ + h * 126 + w];
    }
    __syncthreads();
    for (int idx = t; idx < 64 * 126; idx += 256) {
        int c = idx / 126, w = idx % 126;
        float v = sb[c] + sw[c * 3] * sx[w] + sw[c * 3 + 1] * sx[126 + w]
                        + sw[c * 3 + 2] * sx[252 + w];
        g_x[(size_t)(b * 64 + c) * HW_ + h * 126 + w] = v;
    }
}

// ======================================================================
// split-bf16 helpers + mma core
// ======================================================================
__device__ __forceinline__ void cvt_split(float x, bf16* h, bf16* l) {
    bf16 hh = __float2bfloat16(x);
    *h = hh;
    *l = __float2bfloat16(x - __bfloat162float(hh));
}
__device__ __forceinline__ float gelu_f(float v) {
    return 0.5f * v * (1.0f + erff(v * 0.70710678118654752f));
}

#define LDSM4(R0,R1,R2,R3,ADDR)                                              \
    asm volatile("ldmatrix.sync.aligned.m8n8.x4.shared.b16 {%0,%1,%2,%3}, [%4];" \
        : "=r"(R0),"=r"(R1),"=r"(R2),"=r"(R3) : "r"(ADDR))

#define LDSM4T(R0,R1,R2,R3,ADDR)                                             \
    asm volatile("ldmatrix.sync.aligned.m8n8.x4.trans.shared.b16 {%0,%1,%2,%3}, [%4];" \
        : "=r"(R0),"=r"(R1),"=r"(R2),"=r"(R3) : "r"(ADDR))

#define MMA16816(D,A,B)                                                      \
    asm volatile("mma.sync.aligned.m16n8k16.row.col.f32.bf16.bf16.f32 "      \
        "{%0,%1,%2,%3}, {%4,%5,%6,%7}, {%8,%9}, {%0,%1,%2,%3};"              \
        : "+f"((D)[0]),"+f"((D)[1]),"+f"((D)[2]),"+f"((D)[3])                \
        : "r"((A)[0]),"r"((A)[1]),"r"((A)[2]),"r"((A)[3]),                   \
          "r"((B)[0]),"r"((B)[1]))

// Warp computes 32(M) x 32(N); K = KSTEPS*16. 3 MMAs per tile (split-bf16).
template<int SA, int SB, int KSTEPS>
__device__ __forceinline__ void mma_core(
    const bf16* Ah, const bf16* Al, const bf16* Bh, const bf16* Bl,
    int m0w, int n0w, int lane, float (&acc)[2][4][4])
{
    unsigned baAh = (unsigned)__cvta_generic_to_shared(Ah);
    unsigned baAl = (unsigned)__cvta_generic_to_shared(Al);
    unsigned baBh = (unsigned)__cvta_generic_to_shared(Bh);
    unsigned baBl = (unsigned)__cvta_generic_to_shared(Bl);
    int aRow = m0w + (lane & 15);
    int aCol = (lane >> 4) << 3;
    int bRow = lane & 15;
    int bCol = n0w + ((lane >> 4) << 3);
#pragma unroll
    for (int ks = 0; ks < KSTEPS; ks++) {
        uint32_t ah[2][4], al[2][4], bh[4][2], bl[4][2];
#pragma unroll
        for (int mt = 0; mt < 2; mt++) {
            unsigned offA = (unsigned)((aRow + mt * 16) * SA + ks * 16 + aCol) * 2u;
            LDSM4(ah[mt][0], ah[mt][1], ah[mt][2], ah[mt][3], baAh + offA);
            LDSM4(al[mt][0], al[mt][1], al[mt][2], al[mt][3], baAl + offA);
        }
#pragma unroll
        for (int np = 0; np < 2; np++) {
            unsigned offB = (unsigned)((ks * 16 + bRow) * SB + bCol + np * 16) * 2u;
            LDSM4T(bh[2*np][0], bh[2*np][1], bh[2*np+1][0], bh[2*np+1][1], baBh + offB);
            LDSM4T(bl[2*np][0], bl[2*np][1], bl[2*np+1][0], bl[2*np+1][1], baBl + offB);
        }
#pragma unroll
        for (int mt = 0; mt < 2; mt++)
#pragma unroll
            for (int nt = 0; nt < 4; nt++) {
                MMA16816(acc[mt][nt], ah[mt], bh[nt]);
                MMA16816(acc[mt][nt], ah[mt], bl[nt]);
                MMA16816(acc[mt][nt], al[mt], bh[nt]);
            }
    }
}

#define SMEM_BIG_ELEMS (128 * 136)

// ======================================================================
// forward width DFT: C[128 rows(2bc x 64h)][128 n] = x[row][w] * fwdW[w][n]
// K=126 padded to 128. 512 thr, warp tile 32x32.
// ======================================================================
__global__ __launch_bounds__(512) void k_fwdW() {
    extern __shared__ __align__(16) char smraw[];
    bf16* Ah = (bf16*)smraw;
    bf16* Al = Ah + SMEM_BIG_ELEMS;
    bf16* Bh = Al + SMEM_BIG_ELEMS;
    bf16* Bl = Bh + SMEM_BIG_ELEMS;
    int t = threadIdx.x, lane = t & 31, warp = t >> 5;
    const float* srcA = g_x + (size_t)blockIdx.x * 128 * 126;
    for (int idx = t; idx < 128 * 128; idx += 512) {
        int m = idx >> 7, k = idx & 127;
        float va = (k < 126) ? srcA[m * 126 + k] : 0.f;
        cvt_split(va, &Ah[m * 136 + k], &Al[m * 136 + k]);
        float vb = (m < 126) ? g_fwdW[m * 128 + k] : 0.f;   // here m=w row, k=n col
        cvt_split(vb, &Bh[m * 136 + k], &Bl[m * 136 + k]);
    }
    __syncthreads();
    int m0w = (warp >> 2) * 32, n0w = (warp & 3) * 32;
    float acc[2][4][4];
#pragma unroll
    for (int a = 0; a < 2; a++)
#pragma unroll
        for (int b = 0; b < 4; b++)
#pragma unroll
            for (int c = 0; c < 4; c++) acc[a][b][c] = 0.f;
    mma_core<136, 136, 8>(Ah, Al, Bh, Bl, m0w, n0w, lane, acc);
    int rb = m0w + (lane >> 2), cb = n0w + (lane & 3) * 2;
#pragma unroll
    for (int mt = 0; mt < 2; mt++)
#pragma unroll
        for (int nt = 0; nt < 4; nt++) {
            int col = cb + nt * 8, ri = col >> 6, kx = col & 63;
            int r0 = rb + mt * 16, r1 = r0 + 8;
            int bc0 = blockIdx.x * 2 + (r0 >> 6), h0 = r0 & 63;
            int bc1 = blockIdx.x * 2 + (r1 >> 6), h1 = r1 & 63;
            *(float2*)(g_s1 + (size_t)bc0 * 8192 + ri * 4096 + h0 * 64 + kx) =
                make_float2(acc[mt][nt][0], acc[mt][nt][1]);
            *(float2*)(g_s1 + (size_t)bc1 * 8192 + ri * 4096 + h1 * 64 + kx) =
                make_float2(acc[mt][nt][2], acc[mt][nt][3]);
        }
}

// ======================================================================
// height transform: C[128 m][128 cols(2bc x 64kx)] = G[m][j] * S[j][col], K=128
// ======================================================================
__global__ __launch_bounds__(512) void k_hdft(int fwd) {
    extern __shared__ __align__(16) char smraw[];
    bf16* Ah = (bf16*)smraw;
    bf16* Al = Ah + SMEM_BIG_ELEMS;
    bf16* Bh = Al + SMEM_BIG_ELEMS;
    bf16* Bl = Bh + SMEM_BIG_ELEMS;
    int t = threadIdx.x, lane = t & 31, warp = t >> 5;
    int bcBase = blockIdx.x * 2;
    const float* gA = fwd ? g_Gf : g_G2f;
    const float* in  = fwd ? g_s1 : g_xf;
    float*       out = fwd ? g_xf : g_s1;
    for (int idx = t; idx < 128 * 128; idx += 512) {
        int m = idx >> 7, k = idx & 127;
        cvt_split(gA[idx], &Ah[m * 136 + k], &Al[m * 136 + k]);
        // B: row m=j, col k=c
        float vb = in[(size_t)(bcBase + (k >> 6)) * 8192 + m * 64 + (k & 63)];
        cvt_split(vb, &Bh[m * 136 + k], &Bl[m * 136 + k]);
    }
    __syncthreads();
    int m0w = (warp >> 2) * 32, n0w = (warp & 3) * 32;
    float acc[2][4][4];
#pragma unroll
    for (int a = 0; a < 2; a++)
#pragma unroll
        for (int b = 0; b < 4; b++)
#pragma unroll
            for (int c = 0; c < 4; c++) acc[a][b][c] = 0.f;
    mma_core<136, 136, 8>(Ah, Al, Bh, Bl, m0w, n0w, lane, acc);
    int rb = m0w + (lane >> 2), cb = n0w + (lane & 3) * 2;
#pragma unroll
    for (int mt = 0; mt < 2; mt++)
#pragma unroll
        for (int nt = 0; nt < 4; nt++) {
            int col = cb + nt * 8;
            int bc = bcBase + (col >> 6), kx = col & 63;
            int r0 = rb + mt * 16, r1 = r0 + 8;
            float d0 = acc[mt][nt][0], d1 = acc[mt][nt][1];
            float d2 = acc[mt][nt][2], d3 = acc[mt][nt][3];
            if (fwd) {
                float2 w0 = *(const float2*)(g_mw + (r0 & 63) * 64 + kx);
                float2 w1 = *(const float2*)(g_mw + (r1 & 63) * 64 + kx);
                d0 *= w0.x; d1 *= w0.y; d2 *= w1.x; d3 *= w1.y;
            }
            *(float2*)(out + (size_t)bc * 8192 + r0 * 64 + kx) = make_float2(d0, d1);
            *(float2*)(out + (size_t)bc * 8192 + r1 * 64 + kx) = make_float2(d2, d3);
        }
}

// ---------------- transpose to mode-major ----------------
__global__ __launch_bounds__(256) void k_t1() {
    __shared__ float s[128 * 65];
    int b = blockIdx.x >> 6, ky = blockIdx.x & 63;
    int t = threadIdx.x;
    for (int idx = t; idx < 8192; idx += 256) {
        int i = idx >> 7, r = idx & 127, ri = r >> 6, kx = r & 63;
        s[(ri * 64 + i) * 65 + kx] =
            g_xf[(size_t)(b * 64 + i) * 8192 + ri * 4096 + ky * 64 + kx];
    }
    __syncthreads();
    for (int idx = t; idx < 8192; idx += 256) {
        int kx = idx >> 7, c = idx & 127;
        g_xfm[(size_t)(ky * 64 + kx) * 16384 + b * 128 + c] = s[c * 65 + kx];
    }
}

// ---------------- transpose back from mode-major ----------------
__global__ __launch_bounds__(256) void k_t2() {
    __shared__ float s[128 * 65];
    int b = blockIdx.x >> 6, ky = blockIdx.x & 63;
    int t = threadIdx.x;
    for (int idx = t; idx < 8192; idx += 256) {
        int kx = idx >> 7, c = idx & 127;
        s[c * 65 + kx] = g_s1[(size_t)(ky * 64 + kx) * 16384 + b * 128 + c];
    }
    __syncthreads();
    for (int idx = t; idx < 8192; idx += 256) {
        int o = idx >> 7, r = idx & 127, ri = r >> 6, kx = r & 63;
        g_xf[(size_t)(b * 64 + o) * 8192 + ri * 4096 + ky * 64 + kx] =
            s[(ri * 64 + o) * 65 + kx];
    }
}

// ---------------- weight fold ----------------
__global__ void k_wt(const float* __restrict__ spec, const float* __restrict__ mlp) {
    __shared__ float tile[32][33];
    int x = blockIdx.x * 32 + threadIdx.x;   // mode
    int yb = blockIdx.y * 32;                // io
#pragma unroll
    for (int j = 0; j < 32; j += 8)
        tile[threadIdx.y + j][threadIdx.x] = spec[(size_t)(yb + threadIdx.y + j) * 4096 + x];
    __syncthreads();
    int io2 = yb + threadIdx.x;
    float madd = mlp[(io2 & 63) * 64 + (io2 >> 6)];
    int mb = blockIdx.x * 32;
#pragma unroll
    for (int j = 0; j < 32; j += 8)
        g_wt[(size_t)(mb + threadIdx.y + j) * 4096 + io2] =
            tile[threadIdx.x][threadIdx.y + j] + madd;
}

// ======================================================================
// per-mode GEMM: C[256 x 64] = X[256 x 64] W[64 x 64], K=64
// 512 thr: warp grid 8(M) x 2(N), warp tile 32x32.
// ======================================================================
__global__ __launch_bounds__(512) void k_sgemm() {
    extern __shared__ __align__(16) char smraw[];
    bf16* Ah = (bf16*)smraw;            // [256][72]
    bf16* Al = Ah + 256 * 72;
    bf16* Bh = Al + 256 * 72;           // [64][72]
    bf16* Bl = Bh + 64 * 72;
    int t = threadIdx.x, lane = t & 31, warp = t >> 5;
    int mode = blockIdx.x;
    const float* asrc = g_xfm + (size_t)mode * 16384;
    const float* wsrc = g_wt + (size_t)mode * 4096;
    for (int idx = t; idx < 256 * 64; idx += 512) {
        int m = idx >> 6, k = idx & 63;
        cvt_split(asrc[idx], &Ah[m * 72 + k], &Al[m * 72 + k]);
    }
    for (int idx = t; idx < 64 * 64; idx += 512) {
        int k = idx >> 6, o = idx & 63;
        cvt_split(wsrc[idx], &Bh[k * 72 + o], &Bl[k * 72 + o]);
    }
    __syncthreads();
    int m0w = (warp >> 1) * 32, n0w = (warp & 1) * 32;
    float acc[2][4][4];
#pragma unroll
    for (int a = 0; a < 2; a++)
#pragma unroll
        for (int b = 0; b < 4; b++)
#pragma unroll
            for (int c = 0; c < 4; c++) acc[a][b][c] = 0.f;
    mma_core<72, 72, 4>(Ah, Al, Bh, Bl, m0w, n0w, lane, acc);
    int rb = m0w + (lane >> 2), cb = n0w + (lane & 3) * 2;
    float* dst = g_s1 + (size_t)mode * 16384;
#pragma unroll
    for (int mt = 0; mt < 2; mt++)
#pragma unroll
        for (int nt = 0; nt < 4; nt++) {
            int col = cb + nt * 8;
            int r0 = rb + mt * 16, r1 = r0 + 8;
            *(float2*)(dst + r0 * 64 + col) = make_float2(acc[mt][nt][0], acc[mt][nt][1]);
            *(float2*)(dst + r1 * 64 + col) = make_float2(acc[mt][nt][2], acc[mt][nt][3]);
        }
}

// ======================================================================
// inverse width + bias + exact GELU: C[128 rows(2bc x 64h)][126 w], K=128
// ======================================================================
__global__ __launch_bounds__(512) void k_inv(const float* __restrict__ sb,
                                             const float* __restrict__ mb_) {
    extern __shared__ __align__(16) char smraw[];
    bf16* Ah = (bf16*)smraw;
    bf16* Al = Ah + SMEM_BIG_ELEMS;
    bf16* Bh = Al + SMEM_BIG_ELEMS;
    bf16* Bl = Bh + SMEM_BIG_ELEMS;
    int t = threadIdx.x, lane = t & 31, warp = t >> 5;
    int bcBase = blockIdx.x * 2;
    for (int idx = t; idx < 128 * 128; idx += 512) {
        int m = idx >> 7, k = idx & 127;
        int bc = bcBase + (m >> 6), h = m & 63;
        float va = g_s1[(size_t)bc * 8192 + (k >> 6) * 4096 + h * 64 + (k & 63)];
        cvt_split(va, &Ah[m * 136 + k], &Al[m * 136 + k]);
        cvt_split(g_invW[idx], &Bh[m * 136 + k], &Bl[m * 136 + k]);
    }
    __syncthreads();
    int m0w = (warp >> 2) * 32, n0w = (warp & 3) * 32;
    float acc[2][4][4];
#pragma unroll
    for (int a = 0; a < 2; a++)
#pragma unroll
        for (int b = 0; b < 4; b++)
#pragma unroll
            for (int c = 0; c < 4; c++) acc[a][b][c] = 0.f;
    mma_core<136, 136, 8>(Ah, Al, Bh, Bl, m0w, n0w, lane, acc);
    int rb = m0w + (lane >> 2), cb = n0w + (lane & 3) * 2;
#pragma unroll
    for (int mt = 0; mt < 2; mt++)
#pragma unroll
        for (int nt = 0; nt < 4; nt++) {
            int col = cb + nt * 8;
            if (col >= 126) continue;
            int r0 = rb + mt * 16, r1 = r0 + 8;
            int bc0 = bcBase + (r0 >> 6), h0 = r0 & 63;
            int bc1 = bcBase + (r1 >> 6), h1 = r1 & 63;
            float bias0 = __ldg(sb + (bc0 & 63)) + __ldg(mb_ + (bc0 & 63));
            float bias1 = __ldg(sb + (bc1 & 63)) + __ldg(mb_ + (bc1 & 63));
            *(float2*)(g_x + (size_t)bc0 * HW_ + h0 * 126 + col) =
                make_float2(gelu_f(acc[mt][nt][0] + bias0), gelu_f(acc[mt][nt][1] + bias0));
            *(float2*)(g_x + (size_t)bc1 * HW_ + h1 * 126 + col) =
                make_float2(gelu_f(acc[mt][nt][2] + bias1), gelu_f(acc[mt][nt][3] + bias1));
        }
}

// ---------------- decoder 1x1 conv 64 -> 1 ----------------
__global__ __launch_bounds__(256) void k_dec(const float* __restrict__ dw,
                                             const float* __restrict__ db,
                                             float* __restrict__ out) {
    __shared__ float sw[64];
    int b = blockIdx.x, t = threadIdx.x;
    if (t < 64) sw[t] = dw[t];
    __syncthreads();
    float bias = __ldg(db);
    for (int p = t; p < HW_; p += 256) {
        float s = bias;
        const float* base = g_x + (size_t)b * 64 * HW_ + p;
#pragma unroll 8
        for (int c = 0; c < 64; c++) s = fmaf(sw[c], base[(size_t)c * HW_], s);
        out[(size_t)b * HW_ + p] = s;
    }
}

extern "C" void kernel_launch(void* const* d_in, const int* in_sizes, int n_in,
                              void* d_out, int out_size) {
    const float* x       = (const float*)d_in[0];
    const float* mode_w  = (const float*)d_in[1];
    const float* enc_w   = (const float*)d_in[2];
    const float* enc_b   = (const float*)d_in[3];
    const float* dec_w   = (const float*)d_in[4];
    const float* dec_b   = (const float*)d_in[5];
    const float* spec_w  = (const float*)d_in[6];
    const float* spec_b  = (const float*)d_in[7];
    const float* mlp_w   = (const float*)d_in[8];
    const float* mlp_b   = (const float*)d_in[9];
    float* out = (float*)d_out;

    const int smemBig = 4 * SMEM_BIG_ELEMS * 2;               // 139,264 B
    const int smemS   = (2 * 256 * 72 + 2 * 64 * 72) * 2;     //  92,160 B
    cudaFuncSetAttribute(k_fwdW,  cudaFuncAttributeMaxDynamicSharedMemorySize, smemBig);
    cudaFuncSetAttribute(k_hdft,  cudaFuncAttributeMaxDynamicSharedMemorySize, smemBig);
    cudaFuncSetAttribute(k_sgemm, cudaFuncAttributeMaxDynamicSharedMemorySize, smemS);
    cudaFuncSetAttribute(k_inv,   cudaFuncAttributeMaxDynamicSharedMemorySize, smemBig);

    k_basis<<<64, 256>>>(mode_w);
    k_enc<<<8192, 256>>>(x, enc_w, enc_b);

    for (int l = 0; l < 4; l++) {
        k_wt<<<dim3(128, 128), dim3(32, 8)>>>(spec_w + (size_t)l * 16777216,
                                              mlp_w + (size_t)l * 4096);
        k_fwdW<<<4096, 512, smemBig>>>();
        k_hdft<<<4096, 512, smemBig>>>(1);
        k_t1<<<8192, 256>>>();
        k_sgemm<<<4096, 512, smemS>>>();
        k_t2<<<8192, 256>>>();
        k_hdft<<<4096, 512, smemBig>>>(0);
        k_inv<<<4096, 512, smemBig>>>(spec_b + l * 64, mlp_b + l * 64);
    }
    k_dec<<<128, 256>>>(dec_w, dec_b, out);
}

// round 10
// speedup vs baseline: 4.0372x; 1.0042x over previous
#include <cuda_runtime.h>
#include <cuda_bf16.h>
#include <math.h>
#include <stdint.h>

#define HW_   8064          // 64*126
#define HWP_  8192          // padded spatial: 64*128
#define BC_   8192          // 128*64
#define NMODE 4096          // 64*64

typedef __nv_bfloat16 bf16;
typedef unsigned int u32;

// ---------------- device scratch ----------------
// spatial (padded [bc][h*128+w], cols 126/127 never written -> stay zero)
__device__ __align__(16) bf16 P0h[BC_ * (size_t)HWP_];
__device__ __align__(16) bf16 P0l[BC_ * (size_t)HWP_];
// freq planes [bc][8192]
__device__ __align__(16) bf16 F1h[BC_ * (size_t)8192];
__device__ __align__(16) bf16 F1l[BC_ * (size_t)8192];
// packed (hi|lo<<16) buffers
__device__ __align__(16) u32  g_p1[BC_ * (size_t)8192];      // bc-major packed (hdft1 out / t2 out)
__device__ __align__(16) u32  g_p2[NMODE * (size_t)16384];   // mode-major packed (t1 out)
__device__ __align__(16) u32  g_p3[NMODE * (size_t)16384];   // mode-major packed (sgemm out)
// folded weights, pre-split
__device__ __align__(16) bf16 WTh[NMODE * (size_t)4096];
__device__ __align__(16) bf16 WTl[NMODE * (size_t)4096];
// basis planes, padded [128][128]
__device__ __align__(16) bf16 BWh[16384],  BWl[16384];    // fwd width  [w][n], rows>=126 zero
__device__ __align__(16) bf16 BIh[16384],  BIl[16384];    // inv width  [n][w], cols>=126 zero
__device__ __align__(16) bf16 BGh[16384],  BGl[16384];    // fwd height [m][j]
__device__ __align__(16) bf16 BG2h[16384], BG2l[16384];   // inv height [m][j]
__device__ float g_mw[4096];

// ---------------- helpers ----------------
__device__ __forceinline__ void splitf(float v, bf16& h, bf16& l) {
    h = __float2bfloat16(v);
    l = __float2bfloat16(v - __bfloat162float(h));
}
__device__ __forceinline__ u32 pack_split(float v) {
    bf16 h, l; splitf(v, h, l);
    return (u32)__bfloat16_as_ushort(h) | ((u32)__bfloat16_as_ushort(l) << 16);
}
__device__ __forceinline__ void split_store2(bf16* H, bf16* L, size_t off, float a, float b) {
    bf16 ha, la, hb, lb; splitf(a, ha, la); splitf(b, hb, lb);
    *(__nv_bfloat162*)(H + off) = __halves2bfloat162(ha, hb);
    *(__nv_bfloat162*)(L + off) = __halves2bfloat162(la, lb);
}
__device__ __forceinline__ u32 prmtf(u32 a, u32 b, u32 s) {
    u32 d; asm("prmt.b32 %0,%1,%2,%3;" : "=r"(d) : "r"(a), "r"(b), "r"(s)); return d;
}
__device__ __forceinline__ float gelu_f(float v) {
    return 0.5f * v * (1.0f + erff(v * 0.70710678118654752f));
}

// ---------------- basis precompute (split planes) ----------------
__global__ void k_basis(const float* __restrict__ mwin) {
    int i = blockIdx.x * blockDim.x + threadIdx.x;
    const double PI2 = 6.283185307179586476925286766559;
    if (i < 16384) {
        int r = i >> 7, c = i & 127;
        // fwd width [w=r][n=c], rows >=126 zero
        float v = 0.f;
        if (r < 126) {
            int k = c & 63;
            double th = PI2 * (double)(k * r) / 126.0;
            v = (c < 64) ? (float)cos(th) : (float)(-sin(th));
        }
        splitf(v, BWh[i], BWl[i]);
        // inv width [n=r][w=c], cols >=126 zero
        float v2 = 0.f;
        if (c < 126) {
            int k = r & 63;
            double a = (k == 0 || k == 63) ? (1.0 / 126.0) : (2.0 / 126.0);
            double th = PI2 * (double)(k * c) / 126.0;
            v2 = (r < 64) ? (float)(a * cos(th)) : (float)(-a * sin(th));
        }
        splitf(v2, BIh[i], BIl[i]);
        // fwd height [m=r][j=c]
        {
            int ky = r & 63, h = c & 63;
            double th = PI2 * (double)(ky * h) / 64.0;
            double cs = cos(th), sn = sin(th);
            float g = (float)((r < 64) ? ((c < 64) ? cs : sn) : ((c < 64) ? -sn : cs));
            splitf(g, BGh[i], BGl[i]);
        }
        // inv height [m=r][j=c] (with 1/64)
        {
            int h = r & 63, ky = c & 63;
            double th = PI2 * (double)(ky * h) / 64.0;
            double cs = cos(th) / 64.0, sn = sin(th) / 64.0;
            float g = (float)((r < 64) ? ((c < 64) ? cs : -sn) : ((c < 64) ? sn : cs));
            splitf(g, BG2h[i], BG2l[i]);
        }
    }
    if (i < 4096) {
        int ky = i >> 6, kx = i & 63;
        float s1 = 1.f / (1.f + expf(-mwin[i]));
        if (kx == 0 || kx == 63) {
            float s2 = 1.f / (1.f + expf(-mwin[(((64 - ky) & 63) << 6) + kx]));
            s1 = 0.5f * (s1 + s2);
        }
        g_mw[i] = s1;
    }
}

// ---------------- encoder 1x1 conv 3 -> 64 (writes split planes) ----------------
__global__ __launch_bounds__(256) void k_enc(const float* __restrict__ xin,
                                             const float* __restrict__ ew,
                                             const float* __restrict__ eb) {
    __shared__ float sx[3 * 126];
    __shared__ float sw[192];
    __shared__ float sb[64];
    int b = blockIdx.x >> 6, h = blockIdx.x & 63;
    int t = threadIdx.x;
    if (t < 192) sw[t] = ew[t];
    if (t < 64)  sb[t] = eb[t];
    for (int idx = t; idx < 378; idx += 256) {
        int j = idx / 126, w = idx % 126;
        sx[idx] = xin[(size_t)(b * 3 + j) * HW_ + h * 126 + w];
    }
    __syncthreads();
    for (int idx = t; idx < 64 * 126; idx += 256) {
        int c = idx / 126, w = idx % 126;
        float v = sb[c] + sw[c * 3] * sx[w] + sw[c * 3 + 1] * sx[126 + w]
                        + sw[c * 3 + 2] * sx[252 + w];
        size_t off = (size_t)(b * 64 + c) * HWP_ + h * 128 + w;
        splitf(v, P0h[off], P0l[off]);
    }
}

// ======================================================================
// mma core (round-9, unchanged): warp tile 32x32, split-bf16 (3 MMAs)
// ======================================================================
#define LDSM4(R0,R1,R2,R3,ADDR)                                              \
    asm volatile("ldmatrix.sync.aligned.m8n8.x4.shared.b16 {%0,%1,%2,%3}, [%4];" \
        : "=r"(R0),"=r"(R1),"=r"(R2),"=r"(R3) : "r"(ADDR))
#define LDSM4T(R0,R1,R2,R3,ADDR)                                             \
    asm volatile("ldmatrix.sync.aligned.m8n8.x4.trans.shared.b16 {%0,%1,%2,%3}, [%4];" \
        : "=r"(R0),"=r"(R1),"=r"(R2),"=r"(R3) : "r"(ADDR))
#define MMA16816(D,A,B)                                                      \
    asm volatile("mma.sync.aligned.m16n8k16.row.col.f32.bf16.bf16.f32 "      \
        "{%0,%1,%2,%3}, {%4,%5,%6,%7}, {%8,%9}, {%0,%1,%2,%3};"              \
        : "+f"((D)[0]),"+f"((D)[1]),"+f"((D)[2]),"+f"((D)[3])                \
        : "r"((A)[0]),"r"((A)[1]),"r"((A)[2]),"r"((A)[3]),                   \
          "r"((B)[0]),"r"((B)[1]))

template<int SA, int SB, int KSTEPS>
__device__ __forceinline__ void mma_core(
    const bf16* Ah, const bf16* Al, const bf16* Bh, const bf16* Bl,
    int m0w, int n0w, int lane, float (&acc)[2][4][4])
{
    unsigned baAh = (unsigned)__cvta_generic_to_shared(Ah);
    unsigned baAl = (unsigned)__cvta_generic_to_shared(Al);
    unsigned baBh = (unsigned)__cvta_generic_to_shared(Bh);
    unsigned baBl = (unsigned)__cvta_generic_to_shared(Bl);
    int aRow = m0w + (lane & 15);
    int aCol = (lane >> 4) << 3;
    int bRow = lane & 15;
    int bCol = n0w + ((lane >> 4) << 3);
#pragma unroll
    for (int ks = 0; ks < KSTEPS; ks++) {
        uint32_t ah[2][4], al[2][4], bh[4][2], bl[4][2];
#pragma unroll
        for (int mt = 0; mt < 2; mt++) {
            unsigned offA = (unsigned)((aRow + mt * 16) * SA + ks * 16 + aCol) * 2u;
            LDSM4(ah[mt][0], ah[mt][1], ah[mt][2], ah[mt][3], baAh + offA);
            LDSM4(al[mt][0], al[mt][1], al[mt][2], al[mt][3], baAl + offA);
        }
#pragma unroll
        for (int np = 0; np < 2; np++) {
            unsigned offB = (unsigned)((ks * 16 + bRow) * SB + bCol + np * 16) * 2u;
            LDSM4T(bh[2*np][0], bh[2*np][1], bh[2*np+1][0], bh[2*np+1][1], baBh + offB);
            LDSM4T(bl[2*np][0], bl[2*np][1], bl[2*np+1][0], bl[2*np+1][1], baBl + offB);
        }
#pragma unroll
        for (int mt = 0; mt < 2; mt++)
#pragma unroll
            for (int nt = 0; nt < 4; nt++) {
                MMA16816(acc[mt][nt], ah[mt], bh[nt]);
                MMA16816(acc[mt][nt], ah[mt], bl[nt]);
                MMA16816(acc[mt][nt], al[mt], bh[nt]);
            }
    }
}

#define SMEM_MAT (128 * 136)
#define ZACC float acc[2][4][4];                                             \
    _Pragma("unroll") for (int a_ = 0; a_ < 2; a_++)                         \
    _Pragma("unroll") for (int b_ = 0; b_ < 4; b_++)                         \
    _Pragma("unroll") for (int c_ = 0; c_ < 4; c_++) acc[a_][b_][c_] = 0.f;

// ======================================================================
// forward width DFT: C[128 rows(2bc x 64h)][128 n], K=128 (padded)
// A: P0 planes direct copy; B: BW planes direct copy. Out: F1 planes.
// ======================================================================
__global__ __launch_bounds__(512) void k_fwdW() {
    extern __shared__ __align__(16) char smraw[];
    bf16* Ah = (bf16*)smraw;
    bf16* Al = Ah + SMEM_MAT;
    bf16* Bh = Al + SMEM_MAT;
    bf16* Bl = Bh + SMEM_MAT;
    int t = threadIdx.x, lane = t & 31, warp = t >> 5;
    const uint4* sAh = (const uint4*)(P0h + (size_t)blockIdx.x * 128 * 128);
    const uint4* sAl = (const uint4*)(P0l + (size_t)blockIdx.x * 128 * 128);
    const uint4* sBh = (const uint4*)BWh;
    const uint4* sBl = (const uint4*)BWl;
    for (int idx = t; idx < 2048; idx += 512) {
        int r = idx >> 4, c = idx & 15;
        *(uint4*)(Ah + r * 136 + c * 8) = sAh[idx];
        *(uint4*)(Al + r * 136 + c * 8) = sAl[idx];
        *(uint4*)(Bh + r * 136 + c * 8) = sBh[idx];
        *(uint4*)(Bl + r * 136 + c * 8) = sBl[idx];
    }
    __syncthreads();
    int m0w = (warp >> 2) * 32, n0w = (warp & 3) * 32;
    ZACC
    mma_core<136, 136, 8>(Ah, Al, Bh, Bl, m0w, n0w, lane, acc);
    int rb = m0w + (lane >> 2), cb = n0w + (lane & 3) * 2;
#pragma unroll
    for (int mt = 0; mt < 2; mt++)
#pragma unroll
        for (int nt = 0; nt < 4; nt++) {
            int col = cb + nt * 8, ri = col >> 6, kx = col & 63;
            int r0 = rb + mt * 16, r1 = r0 + 8;
            int bc0 = blockIdx.x * 2 + (r0 >> 6), h0 = r0 & 63;
            int bc1 = blockIdx.x * 2 + (r1 >> 6), h1 = r1 & 63;
            split_store2(F1h, F1l, (size_t)bc0 * 8192 + ri * 4096 + h0 * 64 + kx,
                         acc[mt][nt][0], acc[mt][nt][1]);
            split_store2(F1h, F1l, (size_t)bc1 * 8192 + ri * 4096 + h1 * 64 + kx,
                         acc[mt][nt][2], acc[mt][nt][3]);
        }
}

// ======================================================================
// height transform: C[128 m][128 cols(2bc x 64kx)], K=128
// fwd=1: A=BG planes, B=F1 planes (copy); out packed g_p1 (*mw)
// fwd=0: A=BG2 planes, B=unpack g_p1; out F1 planes
// ======================================================================
__global__ __launch_bounds__(512) void k_hdft(int fwd) {
    extern __shared__ __align__(16) char smraw[];
    bf16* Ah = (bf16*)smraw;
    bf16* Al = Ah + SMEM_MAT;
    bf16* Bh = Al + SMEM_MAT;
    bf16* Bl = Bh + SMEM_MAT;
    int t = threadIdx.x, lane = t & 31, warp = t >> 5;
    int bcBase = blockIdx.x * 2;
    const uint4* sAh = (const uint4*)(fwd ? BGh : BG2h);
    const uint4* sAl = (const uint4*)(fwd ? BGl : BG2l);
    for (int idx = t; idx < 2048; idx += 512) {
        int r = idx >> 4, c = idx & 15;
        *(uint4*)(Ah + r * 136 + c * 8) = sAh[idx];
        *(uint4*)(Al + r * 136 + c * 8) = sAl[idx];
    }
    if (fwd) {
        for (int idx = t; idx < 2048; idx += 512) {
            int r = idx >> 4, c = idx & 15;
            size_t off = (size_t)(bcBase + (c >> 3)) * 8192 + r * 64 + (c & 7) * 8;
            *(uint4*)(Bh + r * 136 + c * 8) = *(const uint4*)(F1h + off);
            *(uint4*)(Bl + r * 136 + c * 8) = *(const uint4*)(F1l + off);
        }
    } else {
        for (int idx = t; idx < 8192; idx += 512) {
            int r = idx >> 6, pc = idx & 63;
            int col0 = pc * 2;
            uint2 p = *(const uint2*)(g_p1 + (size_t)(bcBase + (col0 >> 6)) * 8192
                                      + r * 64 + (col0 & 63));
            *(u32*)(Bh + r * 136 + col0) = prmtf(p.x, p.y, 0x5410);
            *(u32*)(Bl + r * 136 + col0) = prmtf(p.x, p.y, 0x7632);
        }
    }
    __syncthreads();
    int m0w = (warp >> 2) * 32, n0w = (warp & 3) * 32;
    ZACC
    mma_core<136, 136, 8>(Ah, Al, Bh, Bl, m0w, n0w, lane, acc);
    int rb = m0w + (lane >> 2), cb = n0w + (lane & 3) * 2;
#pragma unroll
    for (int mt = 0; mt < 2; mt++)
#pragma unroll
        for (int nt = 0; nt < 4; nt++) {
            int col = cb + nt * 8;
            int bc = bcBase + (col >> 6), kx = col & 63;
            int r0 = rb + mt * 16, r1 = r0 + 8;
            float d0 = acc[mt][nt][0], d1 = acc[mt][nt][1];
            float d2 = acc[mt][nt][2], d3 = acc[mt][nt][3];
            if (fwd) {
                float2 w0 = *(const float2*)(g_mw + (r0 & 63) * 64 + kx);
                float2 w1 = *(const float2*)(g_mw + (r1 & 63) * 64 + kx);
                d0 *= w0.x; d1 *= w0.y; d2 *= w1.x; d3 *= w1.y;
                *(uint2*)(g_p1 + (size_t)bc * 8192 + r0 * 64 + kx) =
                    make_uint2(pack_split(d0), pack_split(d1));
                *(uint2*)(g_p1 + (size_t)bc * 8192 + r1 * 64 + kx) =
                    make_uint2(pack_split(d2), pack_split(d3));
            } else {
                split_store2(F1h, F1l, (size_t)bc * 8192 + r0 * 64 + kx, d0, d1);
                split_store2(F1h, F1l, (size_t)bc * 8192 + r1 * 64 + kx, d2, d3);
            }
        }
}

// ---------------- transpose to mode-major (packed u32) ----------------
__global__ __launch_bounds__(256) void k_t1() {
    __shared__ u32 s[128 * 65];
    int b = blockIdx.x >> 6, ky = blockIdx.x & 63;
    int t = threadIdx.x;
    for (int idx = t; idx < 8192; idx += 256) {
        int i = idx >> 7, r = idx & 127, ri = r >> 6, kx = r & 63;
        s[(ri * 64 + i) * 65 + kx] =
            g_p1[(size_t)(b * 64 + i) * 8192 + ri * 4096 + ky * 64 + kx];
    }
    __syncthreads();
    for (int idx = t; idx < 8192; idx += 256) {
        int kx = idx >> 7, c = idx & 127;
        g_p2[(size_t)(ky * 64 + kx) * 16384 + b * 128 + c] = s[c * 65 + kx];
    }
}

// ---------------- transpose back from mode-major (packed u32) ----------------
__global__ __launch_bounds__(256) void k_t2() {
    __shared__ u32 s[128 * 65];
    int b = blockIdx.x >> 6, ky = blockIdx.x & 63;
    int t = threadIdx.x;
    for (int idx = t; idx < 8192; idx += 256) {
        int kx = idx >> 7, c = idx & 127;
        s[c * 65 + kx] = g_p3[(size_t)(ky * 64 + kx) * 16384 + b * 128 + c];
    }
    __syncthreads();
    for (int idx = t; idx < 8192; idx += 256) {
        int o = idx >> 7, r = idx & 127, ri = r >> 6, kx = r & 63;
        g_p1[(size_t)(b * 64 + o) * 8192 + ri * 4096 + ky * 64 + kx] =
            s[(ri * 64 + o) * 65 + kx];
    }
}

// ---------------- weight fold (writes split planes) ----------------
__global__ void k_wt(const float* __restrict__ spec, const float* __restrict__ mlp) {
    __shared__ float tile[32][33];
    int x = blockIdx.x * 32 + threadIdx.x;   // mode
    int yb = blockIdx.y * 32;                // io
#pragma unroll
    for (int j = 0; j < 32; j += 8)
        tile[threadIdx.y + j][threadIdx.x] = spec[(size_t)(yb + threadIdx.y + j) * 4096 + x];
    __syncthreads();
    int io2 = yb + threadIdx.x;
    float madd = mlp[(io2 & 63) * 64 + (io2 >> 6)];
    int mb = blockIdx.x * 32;
#pragma unroll
    for (int j = 0; j < 32; j += 8) {
        float v = tile[threadIdx.x][threadIdx.y + j] + madd;
        size_t off = (size_t)(mb + threadIdx.y + j) * 4096 + io2;
        splitf(v, WTh[off], WTl[off]);
    }
}

// ======================================================================
// per-mode GEMM: C[256 x 64] = X[256 x 64] W[64 x 64], K=64
// A: unpack g_p2; B: WT planes copy. Out: packed g_p3.
// ======================================================================
__global__ __launch_bounds__(512) void k_sgemm() {
    extern __shared__ __align__(16) char smraw[];
    bf16* Ah = (bf16*)smraw;            // [256][72]
    bf16* Al = Ah + 256 * 72;
    bf16* Bh = Al + 256 * 72;           // [64][72]
    bf16* Bl = Bh + 64 * 72;
    int t = threadIdx.x, lane = t & 31, warp = t >> 5;
    int mode = blockIdx.x;
    const u32* asrc = g_p2 + (size_t)mode * 16384;
    for (int idx = t; idx < 8192; idx += 512) {
        int r = idx >> 5, pc = idx & 31;
        int col0 = pc * 2;
        uint2 p = *(const uint2*)(asrc + r * 64 + col0);
        *(u32*)(Ah + r * 72 + col0) = prmtf(p.x, p.y, 0x5410);
        *(u32*)(Al + r * 72 + col0) = prmtf(p.x, p.y, 0x7632);
    }
    const uint4* sBh = (const uint4*)(WTh + (size_t)mode * 4096);
    const uint4* sBl = (const uint4*)(WTl + (size_t)mode * 4096);
    for (int idx = t; idx < 512; idx += 512) {
        int r = idx >> 3, c = idx & 7;
        *(uint4*)(Bh + r * 72 + c * 8) = sBh[idx];
        *(uint4*)(Bl + r * 72 + c * 8) = sBl[idx];
    }
    __syncthreads();
    int m0w = (warp >> 1) * 32, n0w = (warp & 1) * 32;
    ZACC
    mma_core<72, 72, 4>(Ah, Al, Bh, Bl, m0w, n0w, lane, acc);
    int rb = m0w + (lane >> 2), cb = n0w + (lane & 3) * 2;
    u32* dst = g_p3 + (size_t)mode * 16384;
#pragma unroll
    for (int mt = 0; mt < 2; mt++)
#pragma unroll
        for (int nt = 0; nt < 4; nt++) {
            int col = cb + nt * 8;
            int r0 = rb + mt * 16, r1 = r0 + 8;
            *(uint2*)(dst + r0 * 64 + col) =
                make_uint2(pack_split(acc[mt][nt][0]), pack_split(acc[mt][nt][1]));
            *(uint2*)(dst + r1 * 64 + col) =
                make_uint2(pack_split(acc[mt][nt][2]), pack_split(acc[mt][nt][3]));
        }
}

// ======================================================================
// inverse width + bias + exact GELU: C[128 rows(2bc x 64h)][126 w], K=128
// A: F1 planes copy; B: BI planes copy. Out: P0 planes (gelu).
// ======================================================================
__global__ __launch_bounds__(512) void k_inv(const float* __restrict__ sb,
                                             const float* __restrict__ mb_) {
    extern __shared__ __align__(16) char smraw[];
    bf16* Ah = (bf16*)smraw;
    bf16* Al = Ah + SMEM_MAT;
    bf16* Bh = Al + SMEM_MAT;
    bf16* Bl = Bh + SMEM_MAT;
    int t = threadIdx.x, lane = t & 31, warp = t >> 5;
    int bcBase = blockIdx.x * 2;
    const uint4* sBh = (const uint4*)BIh;
    const uint4* sBl = (const uint4*)BIl;
    for (int idx = t; idx < 2048; idx += 512) {
        int r = idx >> 4, c = idx & 15;
        int bc = bcBase + (r >> 6), h = r & 63;
        size_t off = (size_t)bc * 8192 + (c >> 3) * 4096 + h * 64 + (c & 7) * 8;
        *(uint4*)(Ah + r * 136 + c * 8) = *(const uint4*)(F1h + off);
        *(uint4*)(Al + r * 136 + c * 8) = *(const uint4*)(F1l + off);
        *(uint4*)(Bh + r * 136 + c * 8) = sBh[idx];
        *(uint4*)(Bl + r * 136 + c * 8) = sBl[idx];
    }
    __syncthreads();
    int m0w = (warp >> 2) * 32, n0w = (warp & 3) * 32;
    ZACC
    mma_core<136, 136, 8>(Ah, Al, Bh, Bl, m0w, n0w, lane, acc);
    int rb = m0w + (lane >> 2), cb = n0w + (lane & 3) * 2;
#pragma unroll
    for (int mt = 0; mt < 2; mt++)
#pragma unroll
        for (int nt = 0; nt < 4; nt++) {
            int col = cb + nt * 8;
            if (col >= 126) continue;
            int r0 = rb + mt * 16, r1 = r0 + 8;
            int bc0 = bcBase + (r0 >> 6), h0 = r0 & 63;
            int bc1 = bcBase + (r1 >> 6), h1 = r1 & 63;
            float bias0 = __ldg(sb + (bc0 & 63)) + __ldg(mb_ + (bc0 & 63));
            float bias1 = __ldg(sb + (bc1 & 63)) + __ldg(mb_ + (bc1 & 63));
            split_store2(P0h, P0l, (size_t)bc0 * HWP_ + h0 * 128 + col,
                         gelu_f(acc[mt][nt][0] + bias0), gelu_f(acc[mt][nt][1] + bias0));
            split_store2(P0h, P0l, (size_t)bc1 * HWP_ + h1 * 128 + col,
                         gelu_f(acc[mt][nt][2] + bias1), gelu_f(acc[mt][nt][3] + bias1));
        }
}

// ---------------- decoder 1x1 conv 64 -> 1 (reads split planes) ----------------
__global__ __launch_bounds__(256) void k_dec(const float* __restrict__ dw,
                                             const float* __restrict__ db,
                                             float* __restrict__ out) {
    __shared__ float sw[64];
    int b = blockIdx.x, t = threadIdx.x;
    if (t < 64) sw[t] = dw[t];
    __syncthreads();
    float bias = __ldg(db);
    for (int p = t; p < HWP_; p += 256) {
        int w = p & 127;
        if (w >= 126) continue;
        int h = p >> 7;
        float s = bias;
        size_t base = (size_t)b * 64 * HWP_ + p;
#pragma unroll 8
        for (int c = 0; c < 64; c++) {
            size_t off = base + (size_t)c * HWP_;
            s = fmaf(sw[c], __bfloat162float(P0h[off]) + __bfloat162float(P0l[off]), s);
        }
        out[(size_t)b * HW_ + h * 126 + w] = s;
    }
}

extern "C" void kernel_launch(void* const* d_in, const int* in_sizes, int n_in,
                              void* d_out, int out_size) {
    const float* x       = (const float*)d_in[0];
    const float* mode_w  = (const float*)d_in[1];
    const float* enc_w   = (const float*)d_in[2];
    const float* enc_b   = (const float*)d_in[3];
    const float* dec_w   = (const float*)d_in[4];
    const float* dec_b   = (const float*)d_in[5];
    const float* spec_w  = (const float*)d_in[6];
    const float* spec_b  = (const float*)d_in[7];
    const float* mlp_w   = (const float*)d_in[8];
    const float* mlp_b   = (const float*)d_in[9];
    float* out = (float*)d_out;

    const int smemBig = 4 * SMEM_MAT * 2;                     // 139,264 B
    const int smemS   = (2 * 256 * 72 + 2 * 64 * 72) * 2;     //  92,160 B
    cudaFuncSetAttribute(k_fwdW,  cudaFuncAttributeMaxDynamicSharedMemorySize, smemBig);
    cudaFuncSetAttribute(k_hdft,  cudaFuncAttributeMaxDynamicSharedMemorySize, smemBig);
    cudaFuncSetAttribute(k_sgemm, cudaFuncAttributeMaxDynamicSharedMemorySize, smemS);
    cudaFuncSetAttribute(k_inv,   cudaFuncAttributeMaxDynamicSharedMemorySize, smemBig);

    k_basis<<<64, 256>>>(mode_w);
    k_enc<<<8192, 256>>>(x, enc_w, enc_b);

    for (int l = 0; l < 4; l++) {
        k_wt<<<dim3(128, 128), dim3(32, 8)>>>(spec_w + (size_t)l * 16777216,
                                              mlp_w + (size_t)l * 4096);
        k_fwdW<<<4096, 512, smemBig>>>();
        k_hdft<<<4096, 512, smemBig>>>(1);
        k_t1<<<8192, 256>>>();
        k_sgemm<<<4096, 512, smemS>>>();
        k_t2<<<8192, 256>>>();
        k_hdft<<<4096, 512, smemBig>>>(0);
        k_inv<<<4096, 512, smemBig>>>(spec_b + l * 64, mlp_b + l * 64);
    }
    k_dec<<<128, 256>>>(dec_w, dec_b, out);
}

// round 11
// speedup vs baseline: 4.6810x; 1.1595x over previous
#include <cuda_runtime.h>
#include <cuda_bf16.h>
#include <math.h>
#include <stdint.h>

#define HW_   8064          // 64*126
#define HWP_  8192          // padded spatial: 64*128
#define BC_   8192          // 128*64
#define NMODE 4096          // 64*64

typedef __nv_bfloat16 bf16;
typedef unsigned int u32;

// ---------------- device scratch ----------------
__device__ __align__(16) bf16 P0h[BC_ * (size_t)HWP_];
__device__ __align__(16) bf16 P0l[BC_ * (size_t)HWP_];
__device__ __align__(16) u32  g_p1[BC_ * (size_t)8192];      // bc-major packed
__device__ __align__(16) u32  g_p2[NMODE * (size_t)16384];   // mode-major packed
__device__ __align__(16) u32  g_p3[NMODE * (size_t)16384];   // mode-major packed
__device__ __align__(16) bf16 WTh[NMODE * (size_t)4096];
__device__ __align__(16) bf16 WTl[NMODE * (size_t)4096];
__device__ __align__(16) bf16 BWh[16384],  BWl[16384];    // fwd width  [w][n]
__device__ __align__(16) bf16 BIh[16384],  BIl[16384];    // inv width  [n][w]
__device__ __align__(16) bf16 BGh[16384],  BGl[16384];    // fwd height [m][j]
__device__ __align__(16) bf16 BG2h[16384], BG2l[16384];   // inv height [m][j]
__device__ float g_mw[4096];

// ---------------- helpers ----------------
__device__ __forceinline__ void splitf(float v, bf16& h, bf16& l) {
    h = __float2bfloat16(v);
    l = __float2bfloat16(v - __bfloat162float(h));
}
__device__ __forceinline__ u32 pack_split(float v) {
    bf16 h, l; splitf(v, h, l);
    return (u32)__bfloat16_as_ushort(h) | ((u32)__bfloat16_as_ushort(l) << 16);
}
__device__ __forceinline__ void split_store2(bf16* H, bf16* L, size_t off, float a, float b) {
    bf16 ha, la, hb, lb; splitf(a, ha, la); splitf(b, hb, lb);
    *(__nv_bfloat162*)(H + off) = __halves2bfloat162(ha, hb);
    *(__nv_bfloat162*)(L + off) = __halves2bfloat162(la, lb);
}
__device__ __forceinline__ u32 prmtf(u32 a, u32 b, u32 s) {
    u32 d; asm("prmt.b32 %0,%1,%2,%3;" : "=r"(d) : "r"(a), "r"(b), "r"(s)); return d;
}
__device__ __forceinline__ float gelu_f(float v) {
    return 0.5f * v * (1.0f + erff(v * 0.70710678118654752f));
}

// ---------------- basis precompute (split planes) ----------------
__global__ void k_basis(const float* __restrict__ mwin) {
    int i = blockIdx.x * blockDim.x + threadIdx.x;
    const double PI2 = 6.283185307179586476925286766559;
    if (i < 16384) {
        int r = i >> 7, c = i & 127;
        float v = 0.f;
        if (r < 126) {
            int k = c & 63;
            double th = PI2 * (double)(k * r) / 126.0;
            v = (c < 64) ? (float)cos(th) : (float)(-sin(th));
        }
        splitf(v, BWh[i], BWl[i]);
        float v2 = 0.f;
        if (c < 126) {
            int k = r & 63;
            double a = (k == 0 || k == 63) ? (1.0 / 126.0) : (2.0 / 126.0);
            double th = PI2 * (double)(k * c) / 126.0;
            v2 = (r < 64) ? (float)(a * cos(th)) : (float)(-a * sin(th));
        }
        splitf(v2, BIh[i], BIl[i]);
        {
            int ky = r & 63, h = c & 63;
            double th = PI2 * (double)(ky * h) / 64.0;
            double cs = cos(th), sn = sin(th);
            float g = (float)((r < 64) ? ((c < 64) ? cs : sn) : ((c < 64) ? -sn : cs));
            splitf(g, BGh[i], BGl[i]);
        }
        {
            int h = r & 63, ky = c & 63;
            double th = PI2 * (double)(ky * h) / 64.0;
            double cs = cos(th) / 64.0, sn = sin(th) / 64.0;
            float g = (float)((r < 64) ? ((c < 64) ? cs : -sn) : ((c < 64) ? sn : cs));
            splitf(g, BG2h[i], BG2l[i]);
        }
    }
    if (i < 4096) {
        int ky = i >> 6, kx = i & 63;
        float s1 = 1.f / (1.f + expf(-mwin[i]));
        if (kx == 0 || kx == 63) {
            float s2 = 1.f / (1.f + expf(-mwin[(((64 - ky) & 63) << 6) + kx]));
            s1 = 0.5f * (s1 + s2);
        }
        g_mw[i] = s1;
    }
}

// ---------------- encoder 1x1 conv 3 -> 64 ----------------
__global__ __launch_bounds__(256) void k_enc(const float* __restrict__ xin,
                                             const float* __restrict__ ew,
                                             const float* __restrict__ eb) {
    __shared__ float sx[3 * 126];
    __shared__ float sw[192];
    __shared__ float sb[64];
    int b = blockIdx.x >> 6, h = blockIdx.x & 63;
    int t = threadIdx.x;
    if (t < 192) sw[t] = ew[t];
    if (t < 64)  sb[t] = eb[t];
    for (int idx = t; idx < 378; idx += 256) {
        int j = idx / 126, w = idx % 126;
        sx[idx] = xin[(size_t)(b * 3 + j) * HW_ + h * 126 + w];
    }
    __syncthreads();
    for (int idx = t; idx < 64 * 126; idx += 256) {
        int c = idx / 126, w = idx % 126;
        float v = sb[c] + sw[c * 3] * sx[w] + sw[c * 3 + 1] * sx[126 + w]
                        + sw[c * 3 + 2] * sx[252 + w];
        size_t off = (size_t)(b * 64 + c) * HWP_ + h * 128 + w;
        splitf(v, P0h[off], P0l[off]);
    }
}

// ======================================================================
// mma core: warp tile 32x32, split-bf16 (3 MMAs)
// ======================================================================
#define LDSM4(R0,R1,R2,R3,ADDR)                                              \
    asm volatile("ldmatrix.sync.aligned.m8n8.x4.shared.b16 {%0,%1,%2,%3}, [%4];" \
        : "=r"(R0),"=r"(R1),"=r"(R2),"=r"(R3) : "r"(ADDR))
#define LDSM4T(R0,R1,R2,R3,ADDR)                                             \
    asm volatile("ldmatrix.sync.aligned.m8n8.x4.trans.shared.b16 {%0,%1,%2,%3}, [%4];" \
        : "=r"(R0),"=r"(R1),"=r"(R2),"=r"(R3) : "r"(ADDR))
#define MMA16816(D,A,B)                                                      \
    asm volatile("mma.sync.aligned.m16n8k16.row.col.f32.bf16.bf16.f32 "      \
        "{%0,%1,%2,%3}, {%4,%5,%6,%7}, {%8,%9}, {%0,%1,%2,%3};"              \
        : "+f"((D)[0]),"+f"((D)[1]),"+f"((D)[2]),"+f"((D)[3])                \
        : "r"((A)[0]),"r"((A)[1]),"r"((A)[2]),"r"((A)[3]),                   \
          "r"((B)[0]),"r"((B)[1]))

template<int SA, int SB, int KSTEPS>
__device__ __forceinline__ void mma_core(
    const bf16* Ah, const bf16* Al, const bf16* Bh, const bf16* Bl,
    int m0w, int n0w, int lane, float (&acc)[2][4][4])
{
    unsigned baAh = (unsigned)__cvta_generic_to_shared(Ah);
    unsigned baAl = (unsigned)__cvta_generic_to_shared(Al);
    unsigned baBh = (unsigned)__cvta_generic_to_shared(Bh);
    unsigned baBl = (unsigned)__cvta_generic_to_shared(Bl);
    int aRow = m0w + (lane & 15);
    int aCol = (lane >> 4) << 3;
    int bRow = lane & 15;
    int bCol = n0w + ((lane >> 4) << 3);
#pragma unroll
    for (int ks = 0; ks < KSTEPS; ks++) {
        uint32_t ah[2][4], al[2][4], bh[4][2], bl[4][2];
#pragma unroll
        for (int mt = 0; mt < 2; mt++) {
            unsigned offA = (unsigned)((aRow + mt * 16) * SA + ks * 16 + aCol) * 2u;
            LDSM4(ah[mt][0], ah[mt][1], ah[mt][2], ah[mt][3], baAh + offA);
            LDSM4(al[mt][0], al[mt][1], al[mt][2], al[mt][3], baAl + offA);
        }
#pragma unroll
        for (int np = 0; np < 2; np++) {
            unsigned offB = (unsigned)((ks * 16 + bRow) * SB + bCol + np * 16) * 2u;
            LDSM4T(bh[2*np][0], bh[2*np][1], bh[2*np+1][0], bh[2*np+1][1], baBh + offB);
            LDSM4T(bl[2*np][0], bl[2*np][1], bl[2*np+1][0], bl[2*np+1][1], baBl + offB);
        }
#pragma unroll
        for (int mt = 0; mt < 2; mt++)
#pragma unroll
            for (int nt = 0; nt < 4; nt++) {
                MMA16816(acc[mt][nt], ah[mt], bh[nt]);
                MMA16816(acc[mt][nt], ah[mt], bl[nt]);
                MMA16816(acc[mt][nt], al[mt], bh[nt]);
            }
    }
}

#define SMEM_MAT (128 * 136)
#define RACC _Pragma("unroll") for (int a_ = 0; a_ < 2; a_++)                \
    _Pragma("unroll") for (int b_ = 0; b_ < 4; b_++)                         \
    _Pragma("unroll") for (int c_ = 0; c_ < 4; c_++) acc[a_][b_][c_] = 0.f;

// ======================================================================
// FUSED forward: widthDFT -> (smem transpose) -> heightDFT*mw -> g_p1
// CTA = 2 bc. MMA1: C1[(bc,h)][(ri,kx)] = P0 * BW. Transpose to
// B2[(ri,h)][(bc,kx)], MMA2: C2[(ri,ky)][(bc,kx)] = BG * B2.
// ======================================================================
__global__ __launch_bounds__(512) void k_fwd_fused() {
    extern __shared__ __align__(16) char smraw[];
    bf16* Ah = (bf16*)smraw;
    bf16* Al = Ah + SMEM_MAT;
    bf16* Bh = Al + SMEM_MAT;
    bf16* Bl = Bh + SMEM_MAT;
    int t = threadIdx.x, lane = t & 31, warp = t >> 5;
    int m0w = (warp >> 2) * 32, n0w = (warp & 3) * 32;
    int rb = m0w + (lane >> 2), cb = n0w + (lane & 3) * 2;
    int bcBase = blockIdx.x * 2;

    // phase 1 staging: A = P0 (2 bc), B = BW
    const uint4* sAh = (const uint4*)(P0h + (size_t)blockIdx.x * 16384);
    const uint4* sAl = (const uint4*)(P0l + (size_t)blockIdx.x * 16384);
    const uint4* sBh = (const uint4*)BWh;
    const uint4* sBl = (const uint4*)BWl;
    for (int idx = t; idx < 2048; idx += 512) {
        int r = idx >> 4, c = idx & 15;
        *(uint4*)(Ah + r * 136 + c * 8) = sAh[idx];
        *(uint4*)(Al + r * 136 + c * 8) = sAl[idx];
        *(uint4*)(Bh + r * 136 + c * 8) = sBh[idx];
        *(uint4*)(Bl + r * 136 + c * 8) = sBl[idx];
    }
    __syncthreads();
    float acc[2][4][4];
    RACC
    mma_core<136, 136, 8>(Ah, Al, Bh, Bl, m0w, n0w, lane, acc);
    __syncthreads();

    // restage: A <- BG planes ; B <- transpose(C1) split
    const uint4* gAh = (const uint4*)BGh;
    const uint4* gAl = (const uint4*)BGl;
    for (int idx = t; idx < 2048; idx += 512) {
        int r = idx >> 4, c = idx & 15;
        *(uint4*)(Ah + r * 136 + c * 8) = gAh[idx];
        *(uint4*)(Al + r * 136 + c * 8) = gAl[idx];
    }
#pragma unroll
    for (int mt = 0; mt < 2; mt++)
#pragma unroll
        for (int nt = 0; nt < 4; nt++) {
            int col = cb + nt * 8;
            int jc = (col >> 6) * 64, c2b = col & 63;
            int r0 = rb + mt * 16, r1 = r0 + 8;
            int j0 = jc + (r0 & 63), c20 = (r0 >> 6) * 64 + c2b;
            int j1 = jc + (r1 & 63), c21 = (r1 >> 6) * 64 + c2b;
            split_store2(Bh, Bl, (size_t)j0 * 136 + c20, acc[mt][nt][0], acc[mt][nt][1]);
            split_store2(Bh, Bl, (size_t)j1 * 136 + c21, acc[mt][nt][2], acc[mt][nt][3]);
        }
    __syncthreads();
    RACC
    mma_core<136, 136, 8>(Ah, Al, Bh, Bl, m0w, n0w, lane, acc);

    // epilogue: rows m=(ri,ky), cols (bc,kx); *mw; pack to g_p1
    int rb2 = rb, cb2 = cb;
#pragma unroll
    for (int mt = 0; mt < 2; mt++)
#pragma unroll
        for (int nt = 0; nt < 4; nt++) {
            int col = cb2 + nt * 8;
            int bc = bcBase + (col >> 6), kx = col & 63;
            int r0 = rb2 + mt * 16, r1 = r0 + 8;
            float2 w0 = *(const float2*)(g_mw + (r0 & 63) * 64 + kx);
            float2 w1 = *(const float2*)(g_mw + (r1 & 63) * 64 + kx);
            *(uint2*)(g_p1 + (size_t)bc * 8192 + r0 * 64 + kx) =
                make_uint2(pack_split(acc[mt][nt][0] * w0.x), pack_split(acc[mt][nt][1] * w0.y));
            *(uint2*)(g_p1 + (size_t)bc * 8192 + r1 * 64 + kx) =
                make_uint2(pack_split(acc[mt][nt][2] * w1.x), pack_split(acc[mt][nt][3] * w1.y));
        }
}

// ======================================================================
// FUSED inverse: heightIDFT -> (smem transpose) -> widthIDFT+bias+GELU -> P0
// CTA = 2 bc. MMA1: C2[(ri2,h)][(bc,kx)] = BG2 * B1(g_p1). Transpose to
// A2[(bc,h)][(ri2,kx)], MMA2: C3[(bc,h)][w] = A2 * BI.
// ======================================================================
__global__ __launch_bounds__(512) void k_inv_fused(const float* __restrict__ sb,
                                                   const float* __restrict__ mb_) {
    extern __shared__ __align__(16) char smraw[];
    bf16* Ah = (bf16*)smraw;
    bf16* Al = Ah + SMEM_MAT;
    bf16* Bh = Al + SMEM_MAT;
    bf16* Bl = Bh + SMEM_MAT;
    int t = threadIdx.x, lane = t & 31, warp = t >> 5;
    int m0w = (warp >> 2) * 32, n0w = (warp & 3) * 32;
    int rb = m0w + (lane >> 2), cb = n0w + (lane & 3) * 2;
    int bcBase = blockIdx.x * 2;

    // phase 1 staging: A = BG2 planes; B = unpack g_p1
    const uint4* gAh = (const uint4*)BG2h;
    const uint4* gAl = (const uint4*)BG2l;
    for (int idx = t; idx < 2048; idx += 512) {
        int r = idx >> 4, c = idx & 15;
        *(uint4*)(Ah + r * 136 + c * 8) = gAh[idx];
        *(uint4*)(Al + r * 136 + c * 8) = gAl[idx];
    }
    for (int idx = t; idx < 8192; idx += 512) {
        int r = idx >> 6, pc = idx & 63;
        int col0 = pc * 2;
        uint2 p = *(const uint2*)(g_p1 + (size_t)(bcBase + (col0 >> 6)) * 8192
                                  + r * 64 + (col0 & 63));
        *(u32*)(Bh + r * 136 + col0) = prmtf(p.x, p.y, 0x5410);
        *(u32*)(Bl + r * 136 + col0) = prmtf(p.x, p.y, 0x7632);
    }
    __syncthreads();
    float acc[2][4][4];
    RACC
    mma_core<136, 136, 8>(Ah, Al, Bh, Bl, m0w, n0w, lane, acc);
    __syncthreads();

    // restage: A <- transpose(C2) split ; B <- BI planes
    const uint4* sBh = (const uint4*)BIh;
    const uint4* sBl = (const uint4*)BIl;
    for (int idx = t; idx < 2048; idx += 512) {
        int r = idx >> 4, c = idx & 15;
        *(uint4*)(Bh + r * 136 + c * 8) = sBh[idx];
        *(uint4*)(Bl + r * 136 + c * 8) = sBl[idx];
    }
#pragma unroll
    for (int mt = 0; mt < 2; mt++)
#pragma unroll
        for (int nt = 0; nt < 4; nt++) {
            int col = cb + nt * 8;
            int rowc = (col >> 6) * 64, c2b = col & 63;
            int r0 = rb + mt * 16, r1 = r0 + 8;
            int a0 = rowc + (r0 & 63), c20 = (r0 >> 6) * 64 + c2b;
            int a1 = rowc + (r1 & 63), c21 = (r1 >> 6) * 64 + c2b;
            split_store2(Ah, Al, (size_t)a0 * 136 + c20, acc[mt][nt][0], acc[mt][nt][1]);
            split_store2(Ah, Al, (size_t)a1 * 136 + c21, acc[mt][nt][2], acc[mt][nt][3]);
        }
    __syncthreads();
    RACC
    mma_core<136, 136, 8>(Ah, Al, Bh, Bl, m0w, n0w, lane, acc);

    // epilogue: rows (bc,h), cols w; bias + exact GELU -> P0 planes
#pragma unroll
    for (int mt = 0; mt < 2; mt++)
#pragma unroll
        for (int nt = 0; nt < 4; nt++) {
            int col = cb + nt * 8;
            if (col >= 126) continue;
            int r0 = rb + mt * 16, r1 = r0 + 8;
            int bc0 = bcBase + (r0 >> 6), h0 = r0 & 63;
            int bc1 = bcBase + (r1 >> 6), h1 = r1 & 63;
            float bias0 = __ldg(sb + (bc0 & 63)) + __ldg(mb_ + (bc0 & 63));
            float bias1 = __ldg(sb + (bc1 & 63)) + __ldg(mb_ + (bc1 & 63));
            split_store2(P0h, P0l, (size_t)bc0 * HWP_ + h0 * 128 + col,
                         gelu_f(acc[mt][nt][0] + bias0), gelu_f(acc[mt][nt][1] + bias0));
            split_store2(P0h, P0l, (size_t)bc1 * HWP_ + h1 * 128 + col,
                         gelu_f(acc[mt][nt][2] + bias1), gelu_f(acc[mt][nt][3] + bias1));
        }
}

// ---------------- transpose to mode-major (packed u32) ----------------
__global__ __launch_bounds__(256) void k_t1() {
    __shared__ u32 s[128 * 65];
    int b = blockIdx.x >> 6, ky = blockIdx.x & 63;
    int t = threadIdx.x;
    for (int idx = t; idx < 8192; idx += 256) {
        int i = idx >> 7, r = idx & 127, ri = r >> 6, kx = r & 63;
        s[(ri * 64 + i) * 65 + kx] =
            g_p1[(size_t)(b * 64 + i) * 8192 + ri * 4096 + ky * 64 + kx];
    }
    __syncthreads();
    for (int idx = t; idx < 8192; idx += 256) {
        int kx = idx >> 7, c = idx & 127;
        g_p2[(size_t)(ky * 64 + kx) * 16384 + b * 128 + c] = s[c * 65 + kx];
    }
}

// ---------------- transpose back from mode-major (packed u32) ----------------
__global__ __launch_bounds__(256) void k_t2() {
    __shared__ u32 s[128 * 65];
    int b = blockIdx.x >> 6, ky = blockIdx.x & 63;
    int t = threadIdx.x;
    for (int idx = t; idx < 8192; idx += 256) {
        int kx = idx >> 7, c = idx & 127;
        s[c * 65 + kx] = g_p3[(size_t)(ky * 64 + kx) * 16384 + b * 128 + c];
    }
    __syncthreads();
    for (int idx = t; idx < 8192; idx += 256) {
        int o = idx >> 7, r = idx & 127, ri = r >> 6, kx = r & 63;
        g_p1[(size_t)(b * 64 + o) * 8192 + ri * 4096 + ky * 64 + kx] =
            s[(ri * 64 + o) * 65 + kx];
    }
}

// ---------------- weight fold (writes split planes) ----------------
__global__ void k_wt(const float* __restrict__ spec, const float* __restrict__ mlp) {
    __shared__ float tile[32][33];
    int x = blockIdx.x * 32 + threadIdx.x;   // mode
    int yb = blockIdx.y * 32;                // io
#pragma unroll
    for (int j = 0; j < 32; j += 8)
        tile[threadIdx.y + j][threadIdx.x] = spec[(size_t)(yb + threadIdx.y + j) * 4096 + x];
    __syncthreads();
    int io2 = yb + threadIdx.x;
    float madd = mlp[(io2 & 63) * 64 + (io2 >> 6)];
    int mb = blockIdx.x * 32;
#pragma unroll
    for (int j = 0; j < 32; j += 8) {
        float v = tile[threadIdx.x][threadIdx.y + j] + madd;
        size_t off = (size_t)(mb + threadIdx.y + j) * 4096 + io2;
        splitf(v, WTh[off], WTl[off]);
    }
}

// ======================================================================
// per-mode GEMM: C[256 x 64] = X[256 x 64] W[64 x 64], K=64
// ======================================================================
__global__ __launch_bounds__(512) void k_sgemm() {
    extern __shared__ __align__(16) char smraw[];
    bf16* Ah = (bf16*)smraw;            // [256][72]
    bf16* Al = Ah + 256 * 72;
    bf16* Bh = Al + 256 * 72;           // [64][72]
    bf16* Bl = Bh + 64 * 72;
    int t = threadIdx.x, lane = t & 31, warp = t >> 5;
    int mode = blockIdx.x;
    const u32* asrc = g_p2 + (size_t)mode * 16384;
    for (int idx = t; idx < 8192; idx += 512) {
        int r = idx >> 5, pc = idx & 31;
        int col0 = pc * 2;
        uint2 p = *(const uint2*)(asrc + r * 64 + col0);
        *(u32*)(Ah + r * 72 + col0) = prmtf(p.x, p.y, 0x5410);
        *(u32*)(Al + r * 72 + col0) = prmtf(p.x, p.y, 0x7632);
    }
    const uint4* sBh = (const uint4*)(WTh + (size_t)mode * 4096);
    const uint4* sBl = (const uint4*)(WTl + (size_t)mode * 4096);
    for (int idx = t; idx < 512; idx += 512) {
        int r = idx >> 3, c = idx & 7;
        *(uint4*)(Bh + r * 72 + c * 8) = sBh[idx];
        *(uint4*)(Bl + r * 72 + c * 8) = sBl[idx];
    }
    __syncthreads();
    int m0w = (warp >> 1) * 32, n0w = (warp & 1) * 32;
    float acc[2][4][4];
    RACC
    mma_core<72, 72, 4>(Ah, Al, Bh, Bl, m0w, n0w, lane, acc);
    int rb = m0w + (lane >> 2), cb = n0w + (lane & 3) * 2;
    u32* dst = g_p3 + (size_t)mode * 16384;
#pragma unroll
    for (int mt = 0; mt < 2; mt++)
#pragma unroll
        for (int nt = 0; nt < 4; nt++) {
            int col = cb + nt * 8;
            int r0 = rb + mt * 16, r1 = r0 + 8;
            *(uint2*)(dst + r0 * 64 + col) =
                make_uint2(pack_split(acc[mt][nt][0]), pack_split(acc[mt][nt][1]));
            *(uint2*)(dst + r1 * 64 + col) =
                make_uint2(pack_split(acc[mt][nt][2]), pack_split(acc[mt][nt][3]));
        }
}

// ---------------- decoder 1x1 conv 64 -> 1 ----------------
__global__ __launch_bounds__(256) void k_dec(const float* __restrict__ dw,
                                             const float* __restrict__ db,
                                             float* __restrict__ out) {
    __shared__ float sw[64];
    int b = blockIdx.x, t = threadIdx.x;
    if (t < 64) sw[t] = dw[t];
    __syncthreads();
    float bias = __ldg(db);
    for (int p = t; p < HWP_; p += 256) {
        int w = p & 127;
        if (w >= 126) continue;
        int h = p >> 7;
        float s = bias;
        size_t base = (size_t)b * 64 * HWP_ + p;
#pragma unroll 8
        for (int c = 0; c < 64; c++) {
            size_t off = base + (size_t)c * HWP_;
            s = fmaf(sw[c], __bfloat162float(P0h[off]) + __bfloat162float(P0l[off]), s);
        }
        out[(size_t)b * HW_ + h * 126 + w] = s;
    }
}

extern "C" void kernel_launch(void* const* d_in, const int* in_sizes, int n_in,
                              void* d_out, int out_size) {
    const float* x       = (const float*)d_in[0];
    const float* mode_w  = (const float*)d_in[1];
    const float* enc_w   = (const float*)d_in[2];
    const float* enc_b   = (const float*)d_in[3];
    const float* dec_w   = (const float*)d_in[4];
    const float* dec_b   = (const float*)d_in[5];
    const float* spec_w  = (const float*)d_in[6];
    const float* spec_b  = (const float*)d_in[7];
    const float* mlp_w   = (const float*)d_in[8];
    const float* mlp_b   = (const float*)d_in[9];
    float* out = (float*)d_out;

    const int smemBig = 4 * SMEM_MAT * 2;                     // 139,264 B
    const int smemS   = (2 * 256 * 72 + 2 * 64 * 72) * 2;     //  92,160 B
    cudaFuncSetAttribute(k_fwd_fused, cudaFuncAttributeMaxDynamicSharedMemorySize, smemBig);
    cudaFuncSetAttribute(k_inv_fused, cudaFuncAttributeMaxDynamicSharedMemorySize, smemBig);
    cudaFuncSetAttribute(k_sgemm,     cudaFuncAttributeMaxDynamicSharedMemorySize, smemS);

    k_basis<<<64, 256>>>(mode_w);
    k_enc<<<8192, 256>>>(x, enc_w, enc_b);

    for (int l = 0; l < 4; l++) {
        k_wt<<<dim3(128, 128), dim3(32, 8)>>>(spec_w + (size_t)l * 16777216,
                                              mlp_w + (size_t)l * 4096);
        k_fwd_fused<<<4096, 512, smemBig>>>();
        k_t1<<<8192, 256>>>();
        k_sgemm<<<4096, 512, smemS>>>();
        k_t2<<<8192, 256>>>();
        k_inv_fused<<<4096, 512, smemBig>>>(spec_b + l * 64, mlp_b + l * 64);
    }
    k_dec<<<128, 256>>>(dec_w, dec_b, out);
}

// round 12
// speedup vs baseline: 4.6892x; 1.0018x over previous
#include <cuda_runtime.h>
#include <cuda_bf16.h>
#include <math.h>
#include <stdint.h>

#define HW_   8064          // 64*126
#define HWP_  8192          // padded spatial: 64*128
#define BC_   8192          // 128*64
#define NMODE 4096          // 64*64

typedef __nv_bfloat16 bf16;
typedef unsigned int u32;

// ---------------- device scratch ----------------
__device__ __align__(16) bf16 P0h[BC_ * (size_t)HWP_];
__device__ __align__(16) bf16 P0l[BC_ * (size_t)HWP_];
__device__ __align__(16) u32  g_p1[BC_ * (size_t)8192];      // bc-major packed
__device__ __align__(16) u32  g_p2[NMODE * (size_t)16384];   // mode-major packed
__device__ __align__(16) u32  g_p3[NMODE * (size_t)16384];   // mode-major packed
__device__ __align__(16) bf16 WTh[NMODE * (size_t)4096];
__device__ __align__(16) bf16 WTl[NMODE * (size_t)4096];
__device__ __align__(16) bf16 BWh[16384],  BWl[16384];    // fwd width  [w][n]
__device__ __align__(16) bf16 BIh[16384],  BIl[16384];    // inv width  [n][w]
__device__ __align__(16) bf16 BGh[16384],  BGl[16384];    // fwd height [m][j]
__device__ __align__(16) bf16 BG2h[16384], BG2l[16384];   // inv height [m][j]
__device__ float g_mw[4096];

// ---------------- helpers ----------------
__device__ __forceinline__ void splitf(float v, bf16& h, bf16& l) {
    h = __float2bfloat16(v);
    l = __float2bfloat16(v - __bfloat162float(h));
}
__device__ __forceinline__ u32 pack_split(float v) {
    bf16 h, l; splitf(v, h, l);
    return (u32)__bfloat16_as_ushort(h) | ((u32)__bfloat16_as_ushort(l) << 16);
}
__device__ __forceinline__ void split_store2(bf16* H, bf16* L, size_t off, float a, float b) {
    bf16 ha, la, hb, lb; splitf(a, ha, la); splitf(b, hb, lb);
    *(__nv_bfloat162*)(H + off) = __halves2bfloat162(ha, hb);
    *(__nv_bfloat162*)(L + off) = __halves2bfloat162(la, lb);
}
__device__ __forceinline__ u32 prmtf(u32 a, u32 b, u32 s) {
    u32 d; asm("prmt.b32 %0,%1,%2,%3;" : "=r"(d) : "r"(a), "r"(b), "r"(s)); return d;
}
__device__ __forceinline__ float gelu_f(float v) {
    return 0.5f * v * (1.0f + erff(v * 0.70710678118654752f));
}

// ---------------- basis precompute (split planes) ----------------
__global__ void k_basis(const float* __restrict__ mwin) {
    int i = blockIdx.x * blockDim.x + threadIdx.x;
    const double PI2 = 6.283185307179586476925286766559;
    if (i < 16384) {
        int r = i >> 7, c = i & 127;
        float v = 0.f;
        if (r < 126) {
            int k = c & 63;
            double th = PI2 * (double)(k * r) / 126.0;
            v = (c < 64) ? (float)cos(th) : (float)(-sin(th));
        }
        splitf(v, BWh[i], BWl[i]);
        float v2 = 0.f;
        if (c < 126) {
            int k = r & 63;
            double a = (k == 0 || k == 63) ? (1.0 / 126.0) : (2.0 / 126.0);
            double th = PI2 * (double)(k * c) / 126.0;
            v2 = (r < 64) ? (float)(a * cos(th)) : (float)(-a * sin(th));
        }
        splitf(v2, BIh[i], BIl[i]);
        {
            int ky = r & 63, h = c & 63;
            double th = PI2 * (double)(ky * h) / 64.0;
            double cs = cos(th), sn = sin(th);
            float g = (float)((r < 64) ? ((c < 64) ? cs : sn) : ((c < 64) ? -sn : cs));
            splitf(g, BGh[i], BGl[i]);
        }
        {
            int h = r & 63, ky = c & 63;
            double th = PI2 * (double)(ky * h) / 64.0;
            double cs = cos(th) / 64.0, sn = sin(th) / 64.0;
            float g = (float)((r < 64) ? ((c < 64) ? cs : -sn) : ((c < 64) ? sn : cs));
            splitf(g, BG2h[i], BG2l[i]);
        }
    }
    if (i < 4096) {
        int ky = i >> 6, kx = i & 63;
        float s1 = 1.f / (1.f + expf(-mwin[i]));
        if (kx == 0 || kx == 63) {
            float s2 = 1.f / (1.f + expf(-mwin[(((64 - ky) & 63) << 6) + kx]));
            s1 = 0.5f * (s1 + s2);
        }
        g_mw[i] = s1;
    }
}

// ---------------- encoder 1x1 conv 3 -> 64 ----------------
__global__ __launch_bounds__(256) void k_enc(const float* __restrict__ xin,
                                             const float* __restrict__ ew,
                                             const float* __restrict__ eb) {
    __shared__ float sx[3 * 126];
    __shared__ float sw[192];
    __shared__ float sb[64];
    int b = blockIdx.x >> 6, h = blockIdx.x & 63;
    int t = threadIdx.x;
    if (t < 192) sw[t] = ew[t];
    if (t < 64)  sb[t] = eb[t];
    for (int idx = t; idx < 378; idx += 256) {
        int j = idx / 126, w = idx % 126;
        sx[idx] = xin[(size_t)(b * 3 + j) * HW_ + h * 126 + w];
    }
    __syncthreads();
    for (int idx = t; idx < 64 * 126; idx += 256) {
        int c = idx / 126, w = idx % 126;
        float v = sb[c] + sw[c * 3] * sx[w] + sw[c * 3 + 1] * sx[126 + w]
                        + sw[c * 3 + 2] * sx[252 + w];
        size_t off = (size_t)(b * 64 + c) * HWP_ + h * 128 + w;
        splitf(v, P0h[off], P0l[off]);
    }
}

// ======================================================================
// mma core: warp tile 32x32, split-bf16 (3 MMAs)
// ======================================================================
#define LDSM4(R0,R1,R2,R3,ADDR)                                              \
    asm volatile("ldmatrix.sync.aligned.m8n8.x4.shared.b16 {%0,%1,%2,%3}, [%4];" \
        : "=r"(R0),"=r"(R1),"=r"(R2),"=r"(R3) : "r"(ADDR))
#define LDSM4T(R0,R1,R2,R3,ADDR)                                             \
    asm volatile("ldmatrix.sync.aligned.m8n8.x4.trans.shared.b16 {%0,%1,%2,%3}, [%4];" \
        : "=r"(R0),"=r"(R1),"=r"(R2),"=r"(R3) : "r"(ADDR))
#define MMA16816(D,A,B)                                                      \
    asm volatile("mma.sync.aligned.m16n8k16.row.col.f32.bf16.bf16.f32 "      \
        "{%0,%1,%2,%3}, {%4,%5,%6,%7}, {%8,%9}, {%0,%1,%2,%3};"              \
        : "+f"((D)[0]),"+f"((D)[1]),"+f"((D)[2]),"+f"((D)[3])                \
        : "r"((A)[0]),"r"((A)[1]),"r"((A)[2]),"r"((A)[3]),                   \
          "r"((B)[0]),"r"((B)[1]))

template<int SA, int SB, int KSTEPS>
__device__ __forceinline__ void mma_core(
    const bf16* Ah, const bf16* Al, const bf16* Bh, const bf16* Bl,
    int m0w, int n0w, int lane, float (&acc)[2][4][4])
{
    unsigned baAh = (unsigned)__cvta_generic_to_shared(Ah);
    unsigned baAl = (unsigned)__cvta_generic_to_shared(Al);
    unsigned baBh = (unsigned)__cvta_generic_to_shared(Bh);
    unsigned baBl = (unsigned)__cvta_generic_to_shared(Bl);
    int aRow = m0w + (lane & 15);
    int aCol = (lane >> 4) << 3;
    int bRow = lane & 15;
    int bCol = n0w + ((lane >> 4) << 3);
#pragma unroll
    for (int ks = 0; ks < KSTEPS; ks++) {
        uint32_t ah[2][4], al[2][4], bh[4][2], bl[4][2];
#pragma unroll
        for (int mt = 0; mt < 2; mt++) {
            unsigned offA = (unsigned)((aRow + mt * 16) * SA + ks * 16 + aCol) * 2u;
            LDSM4(ah[mt][0], ah[mt][1], ah[mt][2], ah[mt][3], baAh + offA);
            LDSM4(al[mt][0], al[mt][1], al[mt][2], al[mt][3], baAl + offA);
        }
#pragma unroll
        for (int np = 0; np < 2; np++) {
            unsigned offB = (unsigned)((ks * 16 + bRow) * SB + bCol + np * 16) * 2u;
            LDSM4T(bh[2*np][0], bh[2*np][1], bh[2*np+1][0], bh[2*np+1][1], baBh + offB);
            LDSM4T(bl[2*np][0], bl[2*np][1], bl[2*np+1][0], bl[2*np+1][1], baBl + offB);
        }
#pragma unroll
        for (int mt = 0; mt < 2; mt++)
#pragma unroll
            for (int nt = 0; nt < 4; nt++) {
                MMA16816(acc[mt][nt], ah[mt], bh[nt]);
                MMA16816(acc[mt][nt], ah[mt], bl[nt]);
                MMA16816(acc[mt][nt], al[mt], bh[nt]);
            }
    }
}

#define SMEM_MAT (128 * 136)
#define RACC _Pragma("unroll") for (int a_ = 0; a_ < 2; a_++)                \
    _Pragma("unroll") for (int b_ = 0; b_ < 4; b_++)                         \
    _Pragma("unroll") for (int c_ = 0; c_ < 4; c_++) acc[a_][b_][c_] = 0.f;

// ======================================================================
// FUSED forward: widthDFT -> (smem transpose) -> heightDFT*mw -> g_p1
// CTA = 2 bc. MMA1: C1[(bc,h)][(ri,kx)] = P0 * BW. Transpose to
// B2[(ri,h)][(bc,kx)], MMA2: C2[(ri,ky)][(bc,kx)] = BG * B2.
// ======================================================================
__global__ __launch_bounds__(512) void k_fwd_fused() {
    extern __shared__ __align__(16) char smraw[];
    bf16* Ah = (bf16*)smraw;
    bf16* Al = Ah + SMEM_MAT;
    bf16* Bh = Al + SMEM_MAT;
    bf16* Bl = Bh + SMEM_MAT;
    int t = threadIdx.x, lane = t & 31, warp = t >> 5;
    int m0w = (warp >> 2) * 32, n0w = (warp & 3) * 32;
    int rb = m0w + (lane >> 2), cb = n0w + (lane & 3) * 2;
    int bcBase = blockIdx.x * 2;

    // phase 1 staging: A = P0 (2 bc), B = BW
    const uint4* sAh = (const uint4*)(P0h + (size_t)blockIdx.x * 16384);
    const uint4* sAl = (const uint4*)(P0l + (size_t)blockIdx.x * 16384);
    const uint4* sBh = (const uint4*)BWh;
    const uint4* sBl = (const uint4*)BWl;
    for (int idx = t; idx < 2048; idx += 512) {
        int r = idx >> 4, c = idx & 15;
        *(uint4*)(Ah + r * 136 + c * 8) = sAh[idx];
        *(uint4*)(Al + r * 136 + c * 8) = sAl[idx];
        *(uint4*)(Bh + r * 136 + c * 8) = sBh[idx];
        *(uint4*)(Bl + r * 136 + c * 8) = sBl[idx];
    }
    __syncthreads();
    float acc[2][4][4];
    RACC
    mma_core<136, 136, 8>(Ah, Al, Bh, Bl, m0w, n0w, lane, acc);
    __syncthreads();

    // restage: A <- BG planes ; B <- transpose(C1) split
    const uint4* gAh = (const uint4*)BGh;
    const uint4* gAl = (const uint4*)BGl;
    for (int idx = t; idx < 2048; idx += 512) {
        int r = idx >> 4, c = idx & 15;
        *(uint4*)(Ah + r * 136 + c * 8) = gAh[idx];
        *(uint4*)(Al + r * 136 + c * 8) = gAl[idx];
    }
#pragma unroll
    for (int mt = 0; mt < 2; mt++)
#pragma unroll
        for (int nt = 0; nt < 4; nt++) {
            int col = cb + nt * 8;
            int jc = (col >> 6) * 64, c2b = col & 63;
            int r0 = rb + mt * 16, r1 = r0 + 8;
            int j0 = jc + (r0 & 63), c20 = (r0 >> 6) * 64 + c2b;
            int j1 = jc + (r1 & 63), c21 = (r1 >> 6) * 64 + c2b;
            split_store2(Bh, Bl, (size_t)j0 * 136 + c20, acc[mt][nt][0], acc[mt][nt][1]);
            split_store2(Bh, Bl, (size_t)j1 * 136 + c21, acc[mt][nt][2], acc[mt][nt][3]);
        }
    __syncthreads();
    RACC
    mma_core<136, 136, 8>(Ah, Al, Bh, Bl, m0w, n0w, lane, acc);

    // epilogue: rows m=(ri,ky), cols (bc,kx); *mw; pack to g_p1
    int rb2 = rb, cb2 = cb;
#pragma unroll
    for (int mt = 0; mt < 2; mt++)
#pragma unroll
        for (int nt = 0; nt < 4; nt++) {
            int col = cb2 + nt * 8;
            int bc = bcBase + (col >> 6), kx = col & 63;
            int r0 = rb2 + mt * 16, r1 = r0 + 8;
            float2 w0 = *(const float2*)(g_mw + (r0 & 63) * 64 + kx);
            float2 w1 = *(const float2*)(g_mw + (r1 & 63) * 64 + kx);
            *(uint2*)(g_p1 + (size_t)bc * 8192 + r0 * 64 + kx) =
                make_uint2(pack_split(acc[mt][nt][0] * w0.x), pack_split(acc[mt][nt][1] * w0.y));
            *(uint2*)(g_p1 + (size_t)bc * 8192 + r1 * 64 + kx) =
                make_uint2(pack_split(acc[mt][nt][2] * w1.x), pack_split(acc[mt][nt][3] * w1.y));
        }
}

// ======================================================================
// FUSED inverse: heightIDFT -> (smem transpose) -> widthIDFT+bias+GELU -> P0
// CTA = 2 bc. MMA1: C2[(ri2,h)][(bc,kx)] = BG2 * B1(g_p1). Transpose to
// A2[(bc,h)][(ri2,kx)], MMA2: C3[(bc,h)][w] = A2 * BI.
// ======================================================================
__global__ __launch_bounds__(512) void k_inv_fused(const float* __restrict__ sb,
                                                   const float* __restrict__ mb_) {
    extern __shared__ __align__(16) char smraw[];
    bf16* Ah = (bf16*)smraw;
    bf16* Al = Ah + SMEM_MAT;
    bf16* Bh = Al + SMEM_MAT;
    bf16* Bl = Bh + SMEM_MAT;
    int t = threadIdx.x, lane = t & 31, warp = t >> 5;
    int m0w = (warp >> 2) * 32, n0w = (warp & 3) * 32;
    int rb = m0w + (lane >> 2), cb = n0w + (lane & 3) * 2;
    int bcBase = blockIdx.x * 2;

    // phase 1 staging: A = BG2 planes; B = unpack g_p1
    const uint4* gAh = (const uint4*)BG2h;
    const uint4* gAl = (const uint4*)BG2l;
    for (int idx = t; idx < 2048; idx += 512) {
        int r = idx >> 4, c = idx & 15;
        *(uint4*)(Ah + r * 136 + c * 8) = gAh[idx];
        *(uint4*)(Al + r * 136 + c * 8) = gAl[idx];
    }
    for (int idx = t; idx < 8192; idx += 512) {
        int r = idx >> 6, pc = idx & 63;
        int col0 = pc * 2;
        uint2 p = *(const uint2*)(g_p1 + (size_t)(bcBase + (col0 >> 6)) * 8192
                                  + r * 64 + (col0 & 63));
        *(u32*)(Bh + r * 136 + col0) = prmtf(p.x, p.y, 0x5410);
        *(u32*)(Bl + r * 136 + col0) = prmtf(p.x, p.y, 0x7632);
    }
    __syncthreads();
    float acc[2][4][4];
    RACC
    mma_core<136, 136, 8>(Ah, Al, Bh, Bl, m0w, n0w, lane, acc);
    __syncthreads();

    // restage: A <- transpose(C2) split ; B <- BI planes
    const uint4* sBh = (const uint4*)BIh;
    const uint4* sBl = (const uint4*)BIl;
    for (int idx = t; idx < 2048; idx += 512) {
        int r = idx >> 4, c = idx & 15;
        *(uint4*)(Bh + r * 136 + c * 8) = sBh[idx];
        *(uint4*)(Bl + r * 136 + c * 8) = sBl[idx];
    }
#pragma unroll
    for (int mt = 0; mt < 2; mt++)
#pragma unroll
        for (int nt = 0; nt < 4; nt++) {
            int col = cb + nt * 8;
            int rowc = (col >> 6) * 64, c2b = col & 63;
            int r0 = rb + mt * 16, r1 = r0 + 8;
            int a0 = rowc + (r0 & 63), c20 = (r0 >> 6) * 64 + c2b;
            int a1 = rowc + (r1 & 63), c21 = (r1 >> 6) * 64 + c2b;
            split_store2(Ah, Al, (size_t)a0 * 136 + c20, acc[mt][nt][0], acc[mt][nt][1]);
            split_store2(Ah, Al, (size_t)a1 * 136 + c21, acc[mt][nt][2], acc[mt][nt][3]);
        }
    __syncthreads();
    RACC
    mma_core<136, 136, 8>(Ah, Al, Bh, Bl, m0w, n0w, lane, acc);

    // epilogue: rows (bc,h), cols w; bias + exact GELU -> P0 planes
#pragma unroll
    for (int mt = 0; mt < 2; mt++)
#pragma unroll
        for (int nt = 0; nt < 4; nt++) {
            int col = cb + nt * 8;
            if (col >= 126) continue;
            int r0 = rb + mt * 16, r1 = r0 + 8;
            int bc0 = bcBase + (r0 >> 6), h0 = r0 & 63;
            int bc1 = bcBase + (r1 >> 6), h1 = r1 & 63;
            float bias0 = __ldg(sb + (bc0 & 63)) + __ldg(mb_ + (bc0 & 63));
            float bias1 = __ldg(sb + (bc1 & 63)) + __ldg(mb_ + (bc1 & 63));
            split_store2(P0h, P0l, (size_t)bc0 * HWP_ + h0 * 128 + col,
                         gelu_f(acc[mt][nt][0] + bias0), gelu_f(acc[mt][nt][1] + bias0));
            split_store2(P0h, P0l, (size_t)bc1 * HWP_ + h1 * 128 + col,
                         gelu_f(acc[mt][nt][2] + bias1), gelu_f(acc[mt][nt][3] + bias1));
        }
}

// ---------------- transpose to mode-major (packed u32) ----------------
__global__ __launch_bounds__(256) void k_t1() {
    __shared__ u32 s[128 * 65];
    int b = blockIdx.x >> 6, ky = blockIdx.x & 63;
    int t = threadIdx.x;
    for (int idx = t; idx < 8192; idx += 256) {
        int i = idx >> 7, r = idx & 127, ri = r >> 6, kx = r & 63;
        s[(ri * 64 + i) * 65 + kx] =
            g_p1[(size_t)(b * 64 + i) * 8192 + ri * 4096 + ky * 64 + kx];
    }
    __syncthreads();
    for (int idx = t; idx < 8192; idx += 256) {
        int kx = idx >> 7, c = idx & 127;
        g_p2[(size_t)(ky * 64 + kx) * 16384 + b * 128 + c] = s[c * 65 + kx];
    }
}

// ---------------- transpose back from mode-major (packed u32) ----------------
__global__ __launch_bounds__(256) void k_t2() {
    __shared__ u32 s[128 * 65];
    int b = blockIdx.x >> 6, ky = blockIdx.x & 63;
    int t = threadIdx.x;
    for (int idx = t; idx < 8192; idx += 256) {
        int kx = idx >> 7, c = idx & 127;
        s[c * 65 + kx] = g_p3[(size_t)(ky * 64 + kx) * 16384 + b * 128 + c];
    }
    __syncthreads();
    for (int idx = t; idx < 8192; idx += 256) {
        int o = idx >> 7, r = idx & 127, ri = r >> 6, kx = r & 63;
        g_p1[(size_t)(b * 64 + o) * 8192 + ri * 4096 + ky * 64 + kx] =
            s[(ri * 64 + o) * 65 + kx];
    }
}

// ---------------- weight fold (writes split planes) ----------------
__global__ void k_wt(const float* __restrict__ spec, const float* __restrict__ mlp) {
    __shared__ float tile[32][33];
    int x = blockIdx.x * 32 + threadIdx.x;   // mode
    int yb = blockIdx.y * 32;                // io
#pragma unroll
    for (int j = 0; j < 32; j += 8)
        tile[threadIdx.y + j][threadIdx.x] = spec[(size_t)(yb + threadIdx.y + j) * 4096 + x];
    __syncthreads();
    int io2 = yb + threadIdx.x;
    float madd = mlp[(io2 & 63) * 64 + (io2 >> 6)];
    int mb = blockIdx.x * 32;
#pragma unroll
    for (int j = 0; j < 32; j += 8) {
        float v = tile[threadIdx.x][threadIdx.y + j] + madd;
        size_t off = (size_t)(mb + threadIdx.y + j) * 4096 + io2;
        splitf(v, WTh[off], WTl[off]);
    }
}

// ======================================================================
// per-mode GEMM: C[256 x 64] = X[256 x 64] W[64 x 64], K=64
// ======================================================================
__global__ __launch_bounds__(512) void k_sgemm() {
    extern __shared__ __align__(16) char smraw[];
    bf16* Ah = (bf16*)smraw;            // [256][72]
    bf16* Al = Ah + 256 * 72;
    bf16* Bh = Al + 256 * 72;           // [64][72]
    bf16* Bl = Bh + 64 * 72;
    int t = threadIdx.x, lane = t & 31, warp = t >> 5;
    int mode = blockIdx.x;
    const u32* asrc = g_p2 + (size_t)mode * 16384;
    for (int idx = t; idx < 8192; idx += 512) {
        int r = idx >> 5, pc = idx & 31;
        int col0 = pc * 2;
        uint2 p = *(const uint2*)(asrc + r * 64 + col0);
        *(u32*)(Ah + r * 72 + col0) = prmtf(p.x, p.y, 0x5410);
        *(u32*)(Al + r * 72 + col0) = prmtf(p.x, p.y, 0x7632);
    }
    const uint4* sBh = (const uint4*)(WTh + (size_t)mode * 4096);
    const uint4* sBl = (const uint4*)(WTl + (size_t)mode * 4096);
    for (int idx = t; idx < 512; idx += 512) {
        int r = idx >> 3, c = idx & 7;
        *(uint4*)(Bh + r * 72 + c * 8) = sBh[idx];
        *(uint4*)(Bl + r * 72 + c * 8) = sBl[idx];
    }
    __syncthreads();
    int m0w = (warp >> 1) * 32, n0w = (warp & 1) * 32;
    float acc[2][4][4];
    RACC
    mma_core<72, 72, 4>(Ah, Al, Bh, Bl, m0w, n0w, lane, acc);
    int rb = m0w + (lane >> 2), cb = n0w + (lane & 3) * 2;
    u32* dst = g_p3 + (size_t)mode * 16384;
#pragma unroll
    for (int mt = 0; mt < 2; mt++)
#pragma unroll
        for (int nt = 0; nt < 4; nt++) {
            int col = cb + nt * 8;
            int r0 = rb + mt * 16, r1 = r0 + 8;
            *(uint2*)(dst + r0 * 64 + col) =
                make_uint2(pack_split(acc[mt][nt][0]), pack_split(acc[mt][nt][1]));
            *(uint2*)(dst + r1 * 64 + col) =
                make_uint2(pack_split(acc[mt][nt][2]), pack_split(acc[mt][nt][3]));
        }
}

// ---------------- decoder 1x1 conv 64 -> 1 ----------------
__global__ __launch_bounds__(256) void k_dec(const float* __restrict__ dw,
                                             const float* __restrict__ db,
                                             float* __restrict__ out) {
    __shared__ float sw[64];
    int b = blockIdx.x, t = threadIdx.x;
    if (t < 64) sw[t] = dw[t];
    __syncthreads();
    float bias = __ldg(db);
    for (int p = t; p < HWP_; p += 256) {
        int w = p & 127;
        if (w >= 126) continue;
        int h = p >> 7;
        float s = bias;
        size_t base = (size_t)b * 64 * HWP_ + p;
#pragma unroll 8
        for (int c = 0; c < 64; c++) {
            size_t off = base + (size_t)c * HWP_;
            s = fmaf(sw[c], __bfloat162float(P0h[off]) + __bfloat162float(P0l[off]), s);
        }
        out[(size_t)b * HW_ + h * 126 + w] = s;
    }
}

extern "C" void kernel_launch(void* const* d_in, const int* in_sizes, int n_in,
                              void* d_out, int out_size) {
    const float* x       = (const float*)d_in[0];
    const float* mode_w  = (const float*)d_in[1];
    const float* enc_w   = (const float*)d_in[2];
    const float* enc_b   = (const float*)d_in[3];
    const float* dec_w   = (const float*)d_in[4];
    const float* dec_b   = (const float*)d_in[5];
    const float* spec_w  = (const float*)d_in[6];
    const float* spec_b  = (const float*)d_in[7];
    const float* mlp_w   = (const float*)d_in[8];
    const float* mlp_b   = (const float*)d_in[9];
    float* out = (float*)d_out;

    const int smemBig = 4 * SMEM_MAT * 2;                     // 139,264 B
    const int smemS   = (2 * 256 * 72 + 2 * 64 * 72) * 2;     //  92,160 B
    cudaFuncSetAttribute(k_fwd_fused, cudaFuncAttributeMaxDynamicSharedMemorySize, smemBig);
    cudaFuncSetAttribute(k_inv_fused, cudaFuncAttributeMaxDynamicSharedMemorySize, smemBig);
    cudaFuncSetAttribute(k_sgemm,     cudaFuncAttributeMaxDynamicSharedMemorySize, smemS);

    k_basis<<<64, 256>>>(mode_w);
    k_enc<<<8192, 256>>>(x, enc_w, enc_b);

    for (int l = 0; l < 4; l++) {
        k_wt<<<dim3(128, 128), dim3(32, 8)>>>(spec_w + (size_t)l * 16777216,
                                              mlp_w + (size_t)l * 4096);
        k_fwd_fused<<<4096, 512, smemBig>>>();
        k_t1<<<8192, 256>>>();
        k_sgemm<<<4096, 512, smemS>>>();
        k_t2<<<8192, 256>>>();
        k_inv_fused<<<4096, 512, smemBig>>>(spec_b + l * 64, mlp_b + l * 64);
    }
    k_dec<<<128, 256>>>(dec_w, dec_b, out);
}